// round 12
// baseline (speedup 1.0000x reference)
#include <cuda_runtime.h>
#include <cuda_fp16.h>

typedef unsigned short h16;    // opaque 16-bit payload (fp16 bits)
typedef unsigned int u32;
typedef unsigned long long u64;

// ---------------------------------------------------------------------------
// Problem constants: B=8, TQ=TK=2048, F=1024, H=1024
// ---------------------------------------------------------------------------
#define MTOT (16384LL * 1024)

static __device__ h16   g_Ef[MTOT];                           // encoder fp16
static __device__ h16   g_Xf[MTOT];                           // query fp16
static __device__ h16   g_Wq[1024*1024];                      // W^T fp16
static __device__ h16   g_Wk[1024*1024];
static __device__ h16   g_Wv[1024*1024];
static __device__ h16   g_Q[MTOT];                            // fp16
static __device__ h16   g_K[MTOT];                            // fp16
static __device__ h16   g_V[MTOT];                            // fp16 [b*2048+t][1024]
static __device__ h16   g_S[8LL * 2048 * 2048];               // scores fp16
static __device__ h16   g_P[8LL * 2048 * 2048];               // probs fp16
static __device__ int   g_mask_mode;

// ---------------------------------------------------------------------------
// PTX helpers (sm_80-era; legal under generic compute_103 target)
// ---------------------------------------------------------------------------
__device__ __forceinline__ u32 smem_u32(const void* p) {
    u32 a;
    asm("{ .reg .u64 t; cvta.to.shared.u64 t, %1; cvt.u32.u64 %0, t; }"
        : "=r"(a) : "l"(p));
    return a;
}
#define CP_ASYNC16(dst, src) \
    asm volatile("cp.async.cg.shared.global [%0], [%1], 16;" \
                 :: "r"(dst), "l"(src) : "memory")
#define CP_COMMIT() asm volatile("cp.async.commit_group;" ::: "memory")
#define CP_WAIT1()  asm volatile("cp.async.wait_group 1;" ::: "memory")

__device__ __forceinline__ void ldsm_x4(u32& r0, u32& r1, u32& r2, u32& r3, u32 a) {
    asm volatile("ldmatrix.sync.aligned.m8n8.x4.shared.b16 {%0,%1,%2,%3}, [%4];"
                 : "=r"(r0), "=r"(r1), "=r"(r2), "=r"(r3) : "r"(a));
}
__device__ __forceinline__ void ldsm_x2(u32& r0, u32& r1, u32 a) {
    asm volatile("ldmatrix.sync.aligned.m8n8.x2.shared.b16 {%0,%1}, [%2];"
                 : "=r"(r0), "=r"(r1) : "r"(a));
}
__device__ __forceinline__ void ldsm_x2t(u32& r0, u32& r1, u32 a) {
    asm volatile("ldmatrix.sync.aligned.m8n8.x2.trans.shared.b16 {%0,%1}, [%2];"
                 : "=r"(r0), "=r"(r1) : "r"(a));
}
__device__ __forceinline__ void mma_f16(float* c, const u32* a, const u32* b) {
    asm volatile(
        "mma.sync.aligned.m16n8k16.row.col.f32.f16.f16.f32 "
        "{%0,%1,%2,%3}, {%4,%5,%6,%7}, {%8,%9}, {%0,%1,%2,%3};"
        : "+f"(c[0]), "+f"(c[1]), "+f"(c[2]), "+f"(c[3])
        : "r"(a[0]), "r"(a[1]), "r"(a[2]), "r"(a[3]), "r"(b[0]), "r"(b[1]));
}

// ---------------------------------------------------------------------------
// GEMM: D[m,n] = sum_k A[m,k]*B'[k,n]   (pure fp16, 1 MMA per k-tile)
//   BT=true : B stored [N][K] -> ldmatrix; BT=false: B [K][N] -> ldmatrix.trans
//   MODE 0: fp16 out + bias;  MODE 2: fp32 out * alpha;  MODE 3: fp16 out * alpha
// CTA tile 128x128, BK=64, 3-stage cp.async pipeline, 256 threads (8 warps
// 2x4), register frag double-buffering.
// ---------------------------------------------------------------------------
#define BM 128
#define BN 128
#define BKK 64
#define APITCH 72                            // 64 + 8 pad (16b units)
#define ABYTES (BM * APITCH * 2)             // 18432
#define BPITCH_T 72
#define BBYTES_T (BN * BPITCH_T * 2)         // 18432
#define BPITCH_N 136                         // 128 + 8 pad
#define BBYTES_N (BKK * BPITCH_N * 2)        // 17408

template <int MODE, bool BT>
__global__ void __launch_bounds__(256, 1)
gemm_mma(const h16* __restrict__ A, const h16* __restrict__ B,
         const float* __restrict__ bias,
         h16* __restrict__ C0, float* __restrict__ Cf,
         int lda, int ldb, int ldc, int K, float alpha,
         long long sA, long long sB, long long sC)
{
    constexpr int BBYTES  = BT ? BBYTES_T : BBYTES_N;
    constexpr int OFF_B   = ABYTES;
    constexpr int STAGE   = ABYTES + BBYTES;

    extern __shared__ char smem[];
    const u32 sb = smem_u32(smem);

    const int tid  = threadIdx.x;
    const int wid  = tid >> 5, lane = tid & 31;
    const int wm   = wid & 1, wn = wid >> 1;          // 2 x 4 warp grid
    const long long z = blockIdx.z;
    A += z * sA;
    B += z * sB;

    const int m0 = blockIdx.y * BM;
    const int n0 = blockIdx.x * BN;

    // ---- loader geometry (BK=64, 256 threads) ----
    const int ar0 = tid >> 2, ac = (tid & 3) * 16;
    const int nr0 = tid >> 4, nc = (tid & 15) * 8;

    auto load_stage = [&](int t) {
        const long long kb = (long long)t * BKK;
        const u32 st = sb + (u32)((t % 3) * STAGE);
#pragma unroll
        for (int i = 0; i < 2; i++) {
            const int r = ar0 + i * 64;
            const long long g = (long long)(m0 + r) * lda + kb + ac;
            const u32 d = st + (u32)(r * APITCH + ac) * 2;
            CP_ASYNC16(d,      A + g);
            CP_ASYNC16(d + 16, A + g + 8);
        }
        if (BT) {
#pragma unroll
            for (int i = 0; i < 2; i++) {
                const int r = ar0 + i * 64;
                const long long g = (long long)(n0 + r) * ldb + kb + ac;
                const u32 d = st + OFF_B + (u32)(r * BPITCH_T + ac) * 2;
                CP_ASYNC16(d,      B + g);
                CP_ASYNC16(d + 16, B + g + 8);
            }
        } else {
#pragma unroll
            for (int i = 0; i < 4; i++) {
                const int r = nr0 + i * 16;
                const long long g = (kb + r) * (long long)ldb + n0 + nc;
                const u32 d = st + OFF_B + (u32)(r * BPITCH_N + nc) * 2;
                CP_ASYNC16(d, B + g);
            }
        }
    };

    // ---- ldmatrix per-lane offsets ----
    const int a_lr = (lane & 7) + ((lane >> 3) & 1) * 8;
    const int a_lk = (lane >> 4) * 8;
    u32 a_off[4];
#pragma unroll
    for (int mt = 0; mt < 4; mt++)
        a_off[mt] = (u32)((wm * 64 + mt * 16 + a_lr) * APITCH + a_lk) * 2;

    const int l16 = lane & 15;
    u32 b_off[4];
    if (BT) {
        const int b_nr = l16 & 7, b_k = (l16 >> 3) * 8;
#pragma unroll
        for (int nt = 0; nt < 4; nt++)
            b_off[nt] = (u32)((wn * 32 + nt * 8 + b_nr) * BPITCH_T + b_k) * 2;
    } else {
        const int b_kr = l16;      // 16 k-rows
#pragma unroll
        for (int nt = 0; nt < 4; nt++)
            b_off[nt] = (u32)(b_kr * BPITCH_N + wn * 32 + nt * 8) * 2;
    }

    float acc[4][4][4];
#pragma unroll
    for (int i = 0; i < 4; i++)
#pragma unroll
        for (int j = 0; j < 4; j++)
#pragma unroll
            for (int v = 0; v < 4; v++) acc[i][j][v] = 0.0f;

    // double-buffered fragments
    u32 ah[2][4][4], bh[2][4][2];

    const int nst = K / BKK;

    load_stage(0); CP_COMMIT();
    load_stage(1); CP_COMMIT();

    for (int t = 0; t < nst; t++) {
        CP_WAIT1();
        __syncthreads();
        if (t + 2 < nst) load_stage(t + 2);
        CP_COMMIT();

        const u32 st  = sb + (u32)((t % 3) * STAGE);
        const u32 bAh = st;
        const u32 bBh = st + OFF_B;

        // prime frag buffer 0 (kk = 0)
        {
#pragma unroll
            for (int mt = 0; mt < 4; mt++)
                ldsm_x4(ah[0][mt][0], ah[0][mt][1], ah[0][mt][2], ah[0][mt][3],
                        bAh + a_off[mt]);
#pragma unroll
            for (int nt = 0; nt < 4; nt++) {
                if (BT) ldsm_x2(bh[0][nt][0], bh[0][nt][1], bBh + b_off[nt]);
                else    ldsm_x2t(bh[0][nt][0], bh[0][nt][1], bBh + b_off[nt]);
            }
        }

#pragma unroll
        for (int kk = 0; kk < 4; kk++) {
            const int cur = kk & 1, nxt = cur ^ 1;
            if (kk < 3) {
                const u32 ak = (u32)((kk + 1) * 32);
                const u32 bk = BT ? (u32)((kk + 1) * 32)
                                  : (u32)((kk + 1) * 16 * BPITCH_N * 2);
#pragma unroll
                for (int mt = 0; mt < 4; mt++)
                    ldsm_x4(ah[nxt][mt][0], ah[nxt][mt][1], ah[nxt][mt][2],
                            ah[nxt][mt][3], bAh + a_off[mt] + ak);
#pragma unroll
                for (int nt = 0; nt < 4; nt++) {
                    if (BT) ldsm_x2(bh[nxt][nt][0], bh[nxt][nt][1], bBh + b_off[nt] + bk);
                    else    ldsm_x2t(bh[nxt][nt][0], bh[nxt][nt][1], bBh + b_off[nt] + bk);
                }
            }
#pragma unroll
            for (int mt = 0; mt < 4; mt++)
#pragma unroll
                for (int nt = 0; nt < 4; nt++)
                    mma_f16(acc[mt][nt], ah[cur][mt], bh[cur][nt]);
        }
    }

    // ---- epilogue ----
    const int gr = lane >> 2, gc = (lane & 3) * 2;
#pragma unroll
    for (int mt = 0; mt < 4; mt++) {
#pragma unroll
        for (int nt = 0; nt < 4; nt++) {
            const int m_ = m0 + wm * 64 + mt * 16 + gr;
            const int n_ = n0 + wn * 32 + nt * 8 + gc;
            const float* a4 = acc[mt][nt];
            if (MODE == 0) {
                const float b0 = bias[n_], b1 = bias[n_ + 1];
#pragma unroll
                for (int h = 0; h < 2; h++) {
                    const float v0 = a4[2 * h]     + b0;
                    const float v1 = a4[2 * h + 1] + b1;
                    const long long o = (long long)(m_ + 8 * h) * ldc + n_;
                    h16 hp[2] = { __half_as_ushort(__float2half_rn(v0)),
                                  __half_as_ushort(__float2half_rn(v1)) };
                    *(u32*)(C0 + o) = *(const u32*)hp;
                }
            } else if (MODE == 3) {
                h16* Cz = C0 + z * sC;
#pragma unroll
                for (int h = 0; h < 2; h++) {
                    const long long o = (long long)(m_ + 8 * h) * ldc + n_;
                    h16 hp[2] = { __half_as_ushort(__float2half_rn(a4[2*h]   * alpha)),
                                  __half_as_ushort(__float2half_rn(a4[2*h+1] * alpha)) };
                    *(u32*)(Cz + o) = *(const u32*)hp;
                }
            } else {
                float* Cz = Cf + z * sC;
#pragma unroll
                for (int h = 0; h < 2; h++) {
                    const long long o = (long long)(m_ + 8 * h) * ldc + n_;
                    float2 v = make_float2(a4[2 * h] * alpha, a4[2 * h + 1] * alpha);
                    *(float2*)(Cz + o) = v;
                }
            }
        }
    }
}

// ---------------------------------------------------------------------------
// fp32 -> single fp16 conversion, both activations in one launch
// ---------------------------------------------------------------------------
__global__ void __launch_bounds__(256)
conv_f16_2(const float4* __restrict__ ina, h16* __restrict__ outa,
           const float4* __restrict__ inb, h16* __restrict__ outb)
{
    const bool second = blockIdx.x >= 16384;
    const long long i = ((long long)blockIdx.x - (second ? 16384 : 0)) * 256
                        + threadIdx.x;
    const float4 v = (second ? inb : ina)[i];
    h16 p[4] = { __half_as_ushort(__float2half_rn(v.x)),
                 __half_as_ushort(__float2half_rn(v.y)),
                 __half_as_ushort(__float2half_rn(v.z)),
                 __half_as_ushort(__float2half_rn(v.w)) };
    *(uint2*)&((second ? outb : outa)[i * 4]) = *(const uint2*)p;
}

// W [F=1024, H=1024] -> W^T single fp16 [H, F]; z selects which W
__global__ void wt_conv3(const float* __restrict__ W0, h16* __restrict__ T0,
                         const float* __restrict__ W1, h16* __restrict__ T1,
                         const float* __restrict__ W2, h16* __restrict__ T2)
{
    const float* W = (blockIdx.z == 0) ? W0 : (blockIdx.z == 1) ? W1 : W2;
    h16*         T = (blockIdx.z == 0) ? T0 : (blockIdx.z == 1) ? T1 : T2;
    __shared__ float ts[32][33];
    const int tx = threadIdx.x, ty = threadIdx.y;
    ts[ty][tx] = W[(long long)(blockIdx.y * 32 + ty) * 1024 + blockIdx.x * 32 + tx];
    __syncthreads();
    const float x = ts[tx][ty];
    const long long o = (long long)(blockIdx.x * 32 + ty) * 1024 + blockIdx.y * 32 + tx;
    T[o] = __half_as_ushort(__float2half_rn(x));
}

// ---------------------------------------------------------------------------
// Mask dtype detection (bool may arrive as u8/i32/f32)
// ---------------------------------------------------------------------------
__global__ void detect_mask_kernel(const unsigned char* __restrict__ m)
{
    __shared__ int bad_i32, bad_f32;
    if (threadIdx.x == 0) { bad_i32 = 0; bad_f32 = 0; }
    __syncthreads();
    const unsigned int* w = (const unsigned int*)m;
    for (int i = threadIdx.x; i < 2048; i += 256) {
        unsigned int x = w[i];
        if (x != 0u && x != 1u)          bad_i32 = 1;
        if (x != 0u && x != 0x3F800000u) bad_f32 = 1;
    }
    __syncthreads();
    if (threadIdx.x == 0)
        g_mask_mode = bad_i32 ? (bad_f32 ? 0 : 2) : 1;
}

// ---------------------------------------------------------------------------
// Masked softmax over rows of S (fp16) [B*TQ, 2048] -> P fp16
// Vectorized: u32 pair loads/stores, 8-byte mask loads.
// ---------------------------------------------------------------------------
__global__ void __launch_bounds__(256)
softmax_kernel(const u32* __restrict__ S32, const void* __restrict__ maskv,
               u32* __restrict__ P32)
{
    const long long base32 = (long long)blockIdx.x * 1024;   // 1024 u32 per row
    const int tid  = threadIdx.x;
    const int mode = g_mask_mode;

    float v[8];
    bool  keep[8];
#pragma unroll
    for (int i = 0; i < 4; i++) {
        const long long idx = base32 + tid + i * 256;
        const u32 w = S32[idx];
        const __half2 hv = *(const __half2*)&w;
        v[2*i]   = __half2float(__low2half(hv));
        v[2*i+1] = __half2float(__high2half(hv));
        if (mode == 1) {
            const int2 mm = ((const int2*)maskv)[idx];
            keep[2*i] = mm.x != 0; keep[2*i+1] = mm.y != 0;
        } else if (mode == 2) {
            const float2 mm = ((const float2*)maskv)[idx];
            keep[2*i] = mm.x != 0.0f; keep[2*i+1] = mm.y != 0.0f;
        } else {
            const uchar2 mm = ((const uchar2*)maskv)[idx];
            keep[2*i] = mm.x != 0; keep[2*i+1] = mm.y != 0;
        }
    }

    float mx = -3.0e38f;
#pragma unroll
    for (int i = 0; i < 8; i++)
        if (keep[i]) mx = fmaxf(mx, v[i]);

    __shared__ float red[8];
#pragma unroll
    for (int o = 16; o > 0; o >>= 1)
        mx = fmaxf(mx, __shfl_xor_sync(0xffffffffu, mx, o));
    if ((tid & 31) == 0) red[tid >> 5] = mx;
    __syncthreads();
    float bm = red[0];
#pragma unroll
    for (int i = 1; i < 8; i++) bm = fmaxf(bm, red[i]);

    float sum = 0.0f;
#pragma unroll
    for (int i = 0; i < 8; i++) {
        const float e = keep[i] ? __expf(v[i] - bm) : 0.0f;
        v[i] = e;
        sum += e;
    }
#pragma unroll
    for (int o = 16; o > 0; o >>= 1)
        sum += __shfl_xor_sync(0xffffffffu, sum, o);
    __syncthreads();
    if ((tid & 31) == 0) red[tid >> 5] = sum;
    __syncthreads();
    float ts = 0.0f;
#pragma unroll
    for (int i = 0; i < 8; i++) ts += red[i];

    const float inv = 1.0f / ts;
#pragma unroll
    for (int i = 0; i < 4; i++) {
        const __half2 hp = __floats2half2_rn(v[2*i] * inv, v[2*i+1] * inv);
        P32[base32 + tid + i * 256] = *(const u32*)&hp;
    }
}

// ---------------------------------------------------------------------------
// kernel_launch
// ---------------------------------------------------------------------------
extern "C" void kernel_launch(void* const* d_in, const int* in_sizes, int n_in,
                              void* d_out, int out_size)
{
    (void)in_sizes; (void)n_in; (void)out_size;

    const float* query = (const float*)d_in[0];
    const float* enc   = (const float*)d_in[1];
    const unsigned char* mask = (const unsigned char*)d_in[2];
    const float* Wq = (const float*)d_in[3];
    const float* bq = (const float*)d_in[4];
    const float* Wk = (const float*)d_in[5];
    const float* bk = (const float*)d_in[6];
    const float* Wv = (const float*)d_in[7];
    const float* bv = (const float*)d_in[8];
    float* out = (float*)d_out;

    h16 *Ef, *Xf, *Wqt, *Wkt, *Wvt;
    h16 *Q, *K, *V, *P, *Sp;
    cudaGetSymbolAddress((void**)&Ef,  g_Ef);
    cudaGetSymbolAddress((void**)&Xf,  g_Xf);
    cudaGetSymbolAddress((void**)&Wqt, g_Wq);
    cudaGetSymbolAddress((void**)&Wkt, g_Wk);
    cudaGetSymbolAddress((void**)&Wvt, g_Wv);
    cudaGetSymbolAddress((void**)&Q,   g_Q);
    cudaGetSymbolAddress((void**)&K,   g_K);
    cudaGetSymbolAddress((void**)&V,   g_V);
    cudaGetSymbolAddress((void**)&P,   g_P);
    cudaGetSymbolAddress((void**)&Sp,  g_S);

    constexpr int SMEM_T = 3 * (ABYTES + BBYTES_T);   // 110592
    constexpr int SMEM_N = 3 * (ABYTES + BBYTES_N);   // 107520
    cudaFuncSetAttribute(gemm_mma<0, true>,
                         cudaFuncAttributeMaxDynamicSharedMemorySize, SMEM_T);
    cudaFuncSetAttribute(gemm_mma<3, true>,
                         cudaFuncAttributeMaxDynamicSharedMemorySize, SMEM_T);
    cudaFuncSetAttribute(gemm_mma<2, false>,
                         cudaFuncAttributeMaxDynamicSharedMemorySize, SMEM_N);

    const int T = 2048;

    // 1) convert activations to fp16 (one launch for enc + query)
    conv_f16_2<<<32768, 256>>>((const float4*)enc, Ef, (const float4*)query, Xf);

    // 2) transpose+convert all 3 weights (one launch)
    dim3 wtg(32, 32, 3), wtb(32, 32);
    wt_conv3<<<wtg, wtb>>>(Wq, Wqt, Wk, Wkt, Wv, Wvt);

    detect_mask_kernel<<<1, 256>>>(mask);

    // 3) projections: pure fp16, fp16 outputs
    dim3 gp(1024 / BN, 16384 / BM, 1);
    gemm_mma<0, true><<<gp, 256, SMEM_T>>>(Ef, Wkt, bk,
        K, nullptr, 1024, 1024, 1024, 1024, 1.0f, 0, 0, 0);
    gemm_mma<0, true><<<gp, 256, SMEM_T>>>(Ef, Wvt, bv,
        V, nullptr, 1024, 1024, 1024, 1024, 1.0f, 0, 0, 0);
    gemm_mma<0, true><<<gp, 256, SMEM_T>>>(Xf, Wqt, bq,
        Q, nullptr, 1024, 1024, 1024, 1024, 1.0f, 0, 0, 0);

    // 4) scores: S = (Q K^T) / 32, fp16 out
    dim3 gs(T / BN, T / BM, 8);
    gemm_mma<3, true><<<gs, 256, SMEM_T>>>(Q, K, nullptr,
        Sp, nullptr, 1024, 1024, 2048, 1024, 0.03125f,
        2048LL * 1024, 2048LL * 1024, 2048LL * 2048);

    // 5) masked softmax (fp16 in/out)
    softmax_kernel<<<8 * T, 256>>>((const u32*)Sp, (const void*)mask, (u32*)P);

    // 6) output: O = P V   (V NN layout, ldmatrix.trans), fp32 out
    dim3 go(1024 / BN, T / BM, 8);
    gemm_mma<2, false><<<go, 256, SMEM_N>>>(P, V, nullptr,
        nullptr, out, 2048, 1024, 1024, 2048, 1.0f,
        2048LL * 2048, 2048LL * 1024, 2048LL * 1024);
}

// round 13
// speedup vs baseline: 1.4910x; 1.4910x over previous
#include <cuda_runtime.h>
#include <cuda_fp16.h>

typedef unsigned short h16;    // opaque 16-bit payload (fp16 bits)
typedef unsigned int u32;
typedef unsigned long long u64;

// ---------------------------------------------------------------------------
// Problem constants: B=8, TQ=TK=2048, F=1024, H=1024
// ---------------------------------------------------------------------------
#define MTOT (16384LL * 1024)

static __device__ h16   g_Ef[MTOT];                           // encoder fp16
static __device__ h16   g_Xf[MTOT];                           // query fp16
static __device__ h16   g_Wq[1024*1024];                      // W^T fp16
static __device__ h16   g_Wk[1024*1024];
static __device__ h16   g_Wv[1024*1024];
static __device__ h16   g_Q[MTOT];                            // fp16
static __device__ h16   g_K[MTOT];                            // fp16
static __device__ h16   g_V[MTOT];                            // fp16 [b*2048+t][1024]
static __device__ float g_S[8LL * 2048 * 2048];               // scores fp32
static __device__ h16   g_P[8LL * 2048 * 2048];               // probs fp16
static __device__ int   g_mask_mode;

// ---------------------------------------------------------------------------
// PTX helpers (sm_80-era; legal under generic compute_103 target)
// ---------------------------------------------------------------------------
__device__ __forceinline__ u32 smem_u32(const void* p) {
    u32 a;
    asm("{ .reg .u64 t; cvta.to.shared.u64 t, %1; cvt.u32.u64 %0, t; }"
        : "=r"(a) : "l"(p));
    return a;
}
#define CP_ASYNC16(dst, src) \
    asm volatile("cp.async.cg.shared.global [%0], [%1], 16;" \
                 :: "r"(dst), "l"(src) : "memory")
#define CP_COMMIT() asm volatile("cp.async.commit_group;" ::: "memory")
#define CP_WAIT1()  asm volatile("cp.async.wait_group 1;" ::: "memory")

__device__ __forceinline__ void ldsm_x4(u32& r0, u32& r1, u32& r2, u32& r3, u32 a) {
    asm volatile("ldmatrix.sync.aligned.m8n8.x4.shared.b16 {%0,%1,%2,%3}, [%4];"
                 : "=r"(r0), "=r"(r1), "=r"(r2), "=r"(r3) : "r"(a));
}
__device__ __forceinline__ void ldsm_x2(u32& r0, u32& r1, u32 a) {
    asm volatile("ldmatrix.sync.aligned.m8n8.x2.shared.b16 {%0,%1}, [%2];"
                 : "=r"(r0), "=r"(r1) : "r"(a));
}
__device__ __forceinline__ void ldsm_x2t(u32& r0, u32& r1, u32 a) {
    asm volatile("ldmatrix.sync.aligned.m8n8.x2.trans.shared.b16 {%0,%1}, [%2];"
                 : "=r"(r0), "=r"(r1) : "r"(a));
}
__device__ __forceinline__ void mma_f16(float* c, const u32* a, const u32* b) {
    asm volatile(
        "mma.sync.aligned.m16n8k16.row.col.f32.f16.f16.f32 "
        "{%0,%1,%2,%3}, {%4,%5,%6,%7}, {%8,%9}, {%0,%1,%2,%3};"
        : "+f"(c[0]), "+f"(c[1]), "+f"(c[2]), "+f"(c[3])
        : "r"(a[0]), "r"(a[1]), "r"(a[2]), "r"(a[3]), "r"(b[0]), "r"(b[1]));
}

// ---------------------------------------------------------------------------
// GEMM: D[m,n] = sum_k A[m,k]*B'[k,n]   (pure fp16, 1 MMA per k-tile)
//   BT=true : B stored [N][K] -> ldmatrix; BT=false: B [K][N] -> ldmatrix.trans
//   MODE 0: fp16 out + bias;  MODE 2: fp32 out * alpha
// CTA tile 128x128, BK=64, 3-stage cp.async pipeline, 256 threads (8 warps
// 2x4), register frag double-buffering.   (identical to the 1040.9us R10 run)
// ---------------------------------------------------------------------------
#define BM 128
#define BN 128
#define BKK 64
#define APITCH 72                            // 64 + 8 pad (16b units)
#define ABYTES (BM * APITCH * 2)             // 18432
#define BPITCH_T 72
#define BBYTES_T (BN * BPITCH_T * 2)         // 18432
#define BPITCH_N 136                         // 128 + 8 pad
#define BBYTES_N (BKK * BPITCH_N * 2)        // 17408

template <int MODE, bool BT>
__global__ void __launch_bounds__(256, 1)
gemm_mma(const h16* __restrict__ A, const h16* __restrict__ B,
         const float* __restrict__ bias,
         h16* __restrict__ C0, float* __restrict__ Cf,
         int lda, int ldb, int ldc, int K, float alpha,
         long long sA, long long sB, long long sC)
{
    constexpr int BBYTES  = BT ? BBYTES_T : BBYTES_N;
    constexpr int OFF_B   = ABYTES;
    constexpr int STAGE   = ABYTES + BBYTES;

    extern __shared__ char smem[];
    const u32 sb = smem_u32(smem);

    const int tid  = threadIdx.x;
    const int wid  = tid >> 5, lane = tid & 31;
    const int wm   = wid & 1, wn = wid >> 1;          // 2 x 4 warp grid
    const long long z = blockIdx.z;
    A += z * sA;
    B += z * sB;

    const int m0 = blockIdx.y * BM;
    const int n0 = blockIdx.x * BN;

    // ---- loader geometry (BK=64, 256 threads) ----
    const int ar0 = tid >> 2, ac = (tid & 3) * 16;
    const int nr0 = tid >> 4, nc = (tid & 15) * 8;

    auto load_stage = [&](int t) {
        const long long kb = (long long)t * BKK;
        const u32 st = sb + (u32)((t % 3) * STAGE);
#pragma unroll
        for (int i = 0; i < 2; i++) {
            const int r = ar0 + i * 64;
            const long long g = (long long)(m0 + r) * lda + kb + ac;
            const u32 d = st + (u32)(r * APITCH + ac) * 2;
            CP_ASYNC16(d,      A + g);
            CP_ASYNC16(d + 16, A + g + 8);
        }
        if (BT) {
#pragma unroll
            for (int i = 0; i < 2; i++) {
                const int r = ar0 + i * 64;
                const long long g = (long long)(n0 + r) * ldb + kb + ac;
                const u32 d = st + OFF_B + (u32)(r * BPITCH_T + ac) * 2;
                CP_ASYNC16(d,      B + g);
                CP_ASYNC16(d + 16, B + g + 8);
            }
        } else {
#pragma unroll
            for (int i = 0; i < 4; i++) {
                const int r = nr0 + i * 16;
                const long long g = (kb + r) * (long long)ldb + n0 + nc;
                const u32 d = st + OFF_B + (u32)(r * BPITCH_N + nc) * 2;
                CP_ASYNC16(d, B + g);
            }
        }
    };

    // ---- ldmatrix per-lane offsets ----
    const int a_lr = (lane & 7) + ((lane >> 3) & 1) * 8;
    const int a_lk = (lane >> 4) * 8;
    u32 a_off[4];
#pragma unroll
    for (int mt = 0; mt < 4; mt++)
        a_off[mt] = (u32)((wm * 64 + mt * 16 + a_lr) * APITCH + a_lk) * 2;

    const int l16 = lane & 15;
    u32 b_off[4];
    if (BT) {
        const int b_nr = l16 & 7, b_k = (l16 >> 3) * 8;
#pragma unroll
        for (int nt = 0; nt < 4; nt++)
            b_off[nt] = (u32)((wn * 32 + nt * 8 + b_nr) * BPITCH_T + b_k) * 2;
    } else {
        const int b_kr = l16;      // 16 k-rows
#pragma unroll
        for (int nt = 0; nt < 4; nt++)
            b_off[nt] = (u32)(b_kr * BPITCH_N + wn * 32 + nt * 8) * 2;
    }

    float acc[4][4][4];
#pragma unroll
    for (int i = 0; i < 4; i++)
#pragma unroll
        for (int j = 0; j < 4; j++)
#pragma unroll
            for (int v = 0; v < 4; v++) acc[i][j][v] = 0.0f;

    // double-buffered fragments
    u32 ah[2][4][4], bh[2][4][2];

    const int nst = K / BKK;

    load_stage(0); CP_COMMIT();
    load_stage(1); CP_COMMIT();

    for (int t = 0; t < nst; t++) {
        CP_WAIT1();
        __syncthreads();
        if (t + 2 < nst) load_stage(t + 2);
        CP_COMMIT();

        const u32 st  = sb + (u32)((t % 3) * STAGE);
        const u32 bAh = st;
        const u32 bBh = st + OFF_B;

        // prime frag buffer 0 (kk = 0)
        {
#pragma unroll
            for (int mt = 0; mt < 4; mt++)
                ldsm_x4(ah[0][mt][0], ah[0][mt][1], ah[0][mt][2], ah[0][mt][3],
                        bAh + a_off[mt]);
#pragma unroll
            for (int nt = 0; nt < 4; nt++) {
                if (BT) ldsm_x2(bh[0][nt][0], bh[0][nt][1], bBh + b_off[nt]);
                else    ldsm_x2t(bh[0][nt][0], bh[0][nt][1], bBh + b_off[nt]);
            }
        }

#pragma unroll
        for (int kk = 0; kk < 4; kk++) {
            const int cur = kk & 1, nxt = cur ^ 1;
            if (kk < 3) {
                const u32 ak = (u32)((kk + 1) * 32);
                const u32 bk = BT ? (u32)((kk + 1) * 32)
                                  : (u32)((kk + 1) * 16 * BPITCH_N * 2);
#pragma unroll
                for (int mt = 0; mt < 4; mt++)
                    ldsm_x4(ah[nxt][mt][0], ah[nxt][mt][1], ah[nxt][mt][2],
                            ah[nxt][mt][3], bAh + a_off[mt] + ak);
#pragma unroll
                for (int nt = 0; nt < 4; nt++) {
                    if (BT) ldsm_x2(bh[nxt][nt][0], bh[nxt][nt][1], bBh + b_off[nt] + bk);
                    else    ldsm_x2t(bh[nxt][nt][0], bh[nxt][nt][1], bBh + b_off[nt] + bk);
                }
            }
#pragma unroll
            for (int mt = 0; mt < 4; mt++)
#pragma unroll
                for (int nt = 0; nt < 4; nt++)
                    mma_f16(acc[mt][nt], ah[cur][mt], bh[cur][nt]);
        }
    }

    // ---- epilogue ----
    const int gr = lane >> 2, gc = (lane & 3) * 2;
#pragma unroll
    for (int mt = 0; mt < 4; mt++) {
#pragma unroll
        for (int nt = 0; nt < 4; nt++) {
            const int m_ = m0 + wm * 64 + mt * 16 + gr;
            const int n_ = n0 + wn * 32 + nt * 8 + gc;
            const float* a4 = acc[mt][nt];
            if (MODE == 0) {
                const float b0 = bias[n_], b1 = bias[n_ + 1];
#pragma unroll
                for (int h = 0; h < 2; h++) {
                    const float v0 = a4[2 * h]     + b0;
                    const float v1 = a4[2 * h + 1] + b1;
                    const long long o = (long long)(m_ + 8 * h) * ldc + n_;
                    h16 hp[2] = { __half_as_ushort(__float2half_rn(v0)),
                                  __half_as_ushort(__float2half_rn(v1)) };
                    *(u32*)(C0 + o) = *(const u32*)hp;
                }
            } else {
                float* Cz = Cf + z * sC;
#pragma unroll
                for (int h = 0; h < 2; h++) {
                    const long long o = (long long)(m_ + 8 * h) * ldc + n_;
                    float2 v = make_float2(a4[2 * h] * alpha, a4[2 * h + 1] * alpha);
                    *(float2*)(Cz + o) = v;
                }
            }
        }
    }
}

// ---------------------------------------------------------------------------
// fp32 -> single fp16 conversion, both activations in one launch
// ---------------------------------------------------------------------------
__global__ void __launch_bounds__(256)
conv_f16_2(const float4* __restrict__ ina, h16* __restrict__ outa,
           const float4* __restrict__ inb, h16* __restrict__ outb)
{
    const bool second = blockIdx.x >= 16384;
    const long long i = ((long long)blockIdx.x - (second ? 16384 : 0)) * 256
                        + threadIdx.x;
    const float4 v = (second ? inb : ina)[i];
    h16 p[4] = { __half_as_ushort(__float2half_rn(v.x)),
                 __half_as_ushort(__float2half_rn(v.y)),
                 __half_as_ushort(__float2half_rn(v.z)),
                 __half_as_ushort(__float2half_rn(v.w)) };
    *(uint2*)&((second ? outb : outa)[i * 4]) = *(const uint2*)p;
}

// W [F=1024, H=1024] -> W^T single fp16 [H, F]; z selects which W
__global__ void wt_conv3(const float* __restrict__ W0, h16* __restrict__ T0,
                         const float* __restrict__ W1, h16* __restrict__ T1,
                         const float* __restrict__ W2, h16* __restrict__ T2)
{
    const float* W = (blockIdx.z == 0) ? W0 : (blockIdx.z == 1) ? W1 : W2;
    h16*         T = (blockIdx.z == 0) ? T0 : (blockIdx.z == 1) ? T1 : T2;
    __shared__ float ts[32][33];
    const int tx = threadIdx.x, ty = threadIdx.y;
    ts[ty][tx] = W[(long long)(blockIdx.y * 32 + ty) * 1024 + blockIdx.x * 32 + tx];
    __syncthreads();
    const float x = ts[tx][ty];
    const long long o = (long long)(blockIdx.x * 32 + ty) * 1024 + blockIdx.y * 32 + tx;
    T[o] = __half_as_ushort(__float2half_rn(x));
}

// ---------------------------------------------------------------------------
// Mask dtype detection (bool may arrive as u8/i32/f32)
// ---------------------------------------------------------------------------
__global__ void detect_mask_kernel(const unsigned char* __restrict__ m)
{
    __shared__ int bad_i32, bad_f32;
    if (threadIdx.x == 0) { bad_i32 = 0; bad_f32 = 0; }
    __syncthreads();
    const unsigned int* w = (const unsigned int*)m;
    for (int i = threadIdx.x; i < 2048; i += 256) {
        unsigned int x = w[i];
        if (x != 0u && x != 1u)          bad_i32 = 1;
        if (x != 0u && x != 0x3F800000u) bad_f32 = 1;
    }
    __syncthreads();
    if (threadIdx.x == 0)
        g_mask_mode = bad_i32 ? (bad_f32 ? 0 : 2) : 1;
}

// ---------------------------------------------------------------------------
// Masked softmax over rows of S (fp32) [B*TQ, 2048] -> P fp16 (R10 version)
// ---------------------------------------------------------------------------
__global__ void __launch_bounds__(256)
softmax_kernel(const float* __restrict__ S, const void* __restrict__ maskv,
               h16* __restrict__ P)
{
    const int TK = 2048;
    const long long base = (long long)blockIdx.x * TK;
    const float* s = S + base;
    const int tid  = threadIdx.x;
    const int mode = g_mask_mode;

    float v[8];
    bool  keep[8];
#pragma unroll
    for (int i = 0; i < 8; i++) {
        const int idx = tid + i * 256;
        v[i] = s[idx];
        bool kp;
        if (mode == 1)      kp = ((const int*)maskv)[base + idx] != 0;
        else if (mode == 2) kp = ((const float*)maskv)[base + idx] != 0.0f;
        else                kp = ((const unsigned char*)maskv)[base + idx] != 0;
        keep[i] = kp;
    }

    float mx = -3.0e38f;
#pragma unroll
    for (int i = 0; i < 8; i++)
        if (keep[i]) mx = fmaxf(mx, v[i]);

    __shared__ float red[8];
#pragma unroll
    for (int o = 16; o > 0; o >>= 1)
        mx = fmaxf(mx, __shfl_xor_sync(0xffffffffu, mx, o));
    if ((tid & 31) == 0) red[tid >> 5] = mx;
    __syncthreads();
    float bm = red[0];
#pragma unroll
    for (int i = 1; i < 8; i++) bm = fmaxf(bm, red[i]);

    float sum = 0.0f;
#pragma unroll
    for (int i = 0; i < 8; i++) {
        const float e = keep[i] ? __expf(v[i] - bm) : 0.0f;
        v[i] = e;
        sum += e;
    }
#pragma unroll
    for (int o = 16; o > 0; o >>= 1)
        sum += __shfl_xor_sync(0xffffffffu, sum, o);
    __syncthreads();
    if ((tid & 31) == 0) red[tid >> 5] = sum;
    __syncthreads();
    float ts = 0.0f;
#pragma unroll
    for (int i = 0; i < 8; i++) ts += red[i];

    const float inv = 1.0f / ts;
#pragma unroll
    for (int i = 0; i < 8; i++)
        P[base + tid + i * 256] =
            __half_as_ushort(__float2half_rn(v[i] * inv));
}

// ---------------------------------------------------------------------------
// kernel_launch
// ---------------------------------------------------------------------------
extern "C" void kernel_launch(void* const* d_in, const int* in_sizes, int n_in,
                              void* d_out, int out_size)
{
    (void)in_sizes; (void)n_in; (void)out_size;

    const float* query = (const float*)d_in[0];
    const float* enc   = (const float*)d_in[1];
    const unsigned char* mask = (const unsigned char*)d_in[2];
    const float* Wq = (const float*)d_in[3];
    const float* bq = (const float*)d_in[4];
    const float* Wk = (const float*)d_in[5];
    const float* bk = (const float*)d_in[6];
    const float* Wv = (const float*)d_in[7];
    const float* bv = (const float*)d_in[8];
    float* out = (float*)d_out;

    h16 *Ef, *Xf, *Wqt, *Wkt, *Wvt;
    h16 *Q, *K, *V, *P;
    float* Sp;
    cudaGetSymbolAddress((void**)&Ef,  g_Ef);
    cudaGetSymbolAddress((void**)&Xf,  g_Xf);
    cudaGetSymbolAddress((void**)&Wqt, g_Wq);
    cudaGetSymbolAddress((void**)&Wkt, g_Wk);
    cudaGetSymbolAddress((void**)&Wvt, g_Wv);
    cudaGetSymbolAddress((void**)&Q,   g_Q);
    cudaGetSymbolAddress((void**)&K,   g_K);
    cudaGetSymbolAddress((void**)&V,   g_V);
    cudaGetSymbolAddress((void**)&P,   g_P);
    cudaGetSymbolAddress((void**)&Sp,  g_S);

    constexpr int SMEM_T = 3 * (ABYTES + BBYTES_T);   // 110592
    constexpr int SMEM_N = 3 * (ABYTES + BBYTES_N);   // 107520
    cudaFuncSetAttribute(gemm_mma<0, true>,
                         cudaFuncAttributeMaxDynamicSharedMemorySize, SMEM_T);
    cudaFuncSetAttribute(gemm_mma<2, true>,
                         cudaFuncAttributeMaxDynamicSharedMemorySize, SMEM_T);
    cudaFuncSetAttribute(gemm_mma<2, false>,
                         cudaFuncAttributeMaxDynamicSharedMemorySize, SMEM_N);

    const int T = 2048;

    // 1) convert activations to fp16 (one launch for enc + query)
    conv_f16_2<<<32768, 256>>>((const float4*)enc, Ef, (const float4*)query, Xf);

    // 2) transpose+convert all 3 weights (one launch)
    dim3 wtg(32, 32, 3), wtb(32, 32);
    wt_conv3<<<wtg, wtb>>>(Wq, Wqt, Wk, Wkt, Wv, Wvt);

    detect_mask_kernel<<<1, 256>>>(mask);

    // 3) projections: pure fp16, fp16 outputs
    dim3 gp(1024 / BN, 16384 / BM, 1);
    gemm_mma<0, true><<<gp, 256, SMEM_T>>>(Ef, Wkt, bk,
        K, nullptr, 1024, 1024, 1024, 1024, 1.0f, 0, 0, 0);
    gemm_mma<0, true><<<gp, 256, SMEM_T>>>(Ef, Wvt, bv,
        V, nullptr, 1024, 1024, 1024, 1024, 1.0f, 0, 0, 0);
    gemm_mma<0, true><<<gp, 256, SMEM_T>>>(Xf, Wqt, bq,
        Q, nullptr, 1024, 1024, 1024, 1024, 1.0f, 0, 0, 0);

    // 4) scores: S = (Q K^T) / 32, fp32 out
    dim3 gs(T / BN, T / BM, 8);
    gemm_mma<2, true><<<gs, 256, SMEM_T>>>(Q, K, nullptr,
        nullptr, Sp, 1024, 1024, 2048, 1024, 0.03125f,
        2048LL * 1024, 2048LL * 1024, 2048LL * 2048);

    // 5) masked softmax (fp32 in, fp16 out)
    softmax_kernel<<<8 * T, 256>>>(Sp, (const void*)mask, P);

    // 6) output: O = P V   (V NN layout, ldmatrix.trans), fp32 out
    dim3 go(1024 / BN, T / BM, 8);
    gemm_mma<2, false><<<go, 256, SMEM_N>>>(P, V, nullptr,
        nullptr, out, 2048, 1024, 1024, 2048, 1.0f,
        2048LL * 2048, 2048LL * 1024, 2048LL * 1024);
}

// round 14
// speedup vs baseline: 1.8143x; 1.2169x over previous
#include <cuda_runtime.h>
#include <cuda_fp16.h>

typedef unsigned short h16;    // opaque 16-bit payload (fp16 bits)
typedef unsigned int u32;
typedef unsigned long long u64;

// ---------------------------------------------------------------------------
// Problem constants: B=8, TQ=TK=2048, F=1024, H=1024
// ---------------------------------------------------------------------------
#define MTOT (16384LL * 1024)

static __device__ h16   g_Ef[MTOT];                           // encoder fp16
static __device__ h16   g_Xf[MTOT];                           // query fp16
static __device__ h16   g_Wq[1024*1024];                      // W^T fp16
static __device__ h16   g_Wk[1024*1024];
static __device__ h16   g_Wv[1024*1024];
static __device__ h16   g_Q[MTOT];                            // fp16
static __device__ h16   g_K[MTOT];                            // fp16
static __device__ h16   g_V[MTOT];                            // fp16 [b*2048+t][1024]
static __device__ float g_S[8LL * 2048 * 2048];               // scores fp32
static __device__ h16   g_P[8LL * 2048 * 2048];               // probs fp16
static __device__ int   g_mask_mode;

// ---------------------------------------------------------------------------
// PTX helpers (sm_80-era; legal under generic compute_103 target)
// ---------------------------------------------------------------------------
__device__ __forceinline__ u32 smem_u32(const void* p) {
    u32 a;
    asm("{ .reg .u64 t; cvta.to.shared.u64 t, %1; cvt.u32.u64 %0, t; }"
        : "=r"(a) : "l"(p));
    return a;
}
#define CP_ASYNC16(dst, src) \
    asm volatile("cp.async.cg.shared.global [%0], [%1], 16;" \
                 :: "r"(dst), "l"(src) : "memory")
#define CP_COMMIT() asm volatile("cp.async.commit_group;" ::: "memory")
#define CP_WAIT1()  asm volatile("cp.async.wait_group 1;" ::: "memory")

__device__ __forceinline__ void ldsm_x4(u32& r0, u32& r1, u32& r2, u32& r3, u32 a) {
    asm volatile("ldmatrix.sync.aligned.m8n8.x4.shared.b16 {%0,%1,%2,%3}, [%4];"
                 : "=r"(r0), "=r"(r1), "=r"(r2), "=r"(r3) : "r"(a));
}
__device__ __forceinline__ void ldsm_x2(u32& r0, u32& r1, u32 a) {
    asm volatile("ldmatrix.sync.aligned.m8n8.x2.shared.b16 {%0,%1}, [%2];"
                 : "=r"(r0), "=r"(r1) : "r"(a));
}
__device__ __forceinline__ void ldsm_x2t(u32& r0, u32& r1, u32 a) {
    asm volatile("ldmatrix.sync.aligned.m8n8.x2.trans.shared.b16 {%0,%1}, [%2];"
                 : "=r"(r0), "=r"(r1) : "r"(a));
}
__device__ __forceinline__ void mma_f16(float* c, const u32* a, const u32* b) {
    asm volatile(
        "mma.sync.aligned.m16n8k16.row.col.f32.f16.f16.f32 "
        "{%0,%1,%2,%3}, {%4,%5,%6,%7}, {%8,%9}, {%0,%1,%2,%3};"
        : "+f"(c[0]), "+f"(c[1]), "+f"(c[2]), "+f"(c[3])
        : "r"(a[0]), "r"(a[1]), "r"(a[2]), "r"(a[3]), "r"(b[0]), "r"(b[1]));
}

// ---------------------------------------------------------------------------
// GEMM: D[m,n] = sum_k A[m,k]*B'[k,n]   (pure fp16, 1 MMA per k-tile)
//   BT=true : B stored [N][K] -> ldmatrix; BT=false: B [K][N] -> ldmatrix.trans
//   MODE 0: fp16 out + bias;  MODE 2: fp32 out * alpha
// CTA tile 128x128, BK=64, 3-stage cp.async pipeline, 256 threads (8 warps
// 2x4). TWO CTAs per SM (launch_bounds(256,2)); fragments single-buffered
// (the co-resident CTA hides LDSM->MMA latency; saves regs to fit 128/thread).
// ---------------------------------------------------------------------------
#define BM 128
#define BN 128
#define BKK 64
#define APITCH 72                            // 64 + 8 pad (16b units)
#define ABYTES (BM * APITCH * 2)             // 18432
#define BPITCH_T 72
#define BBYTES_T (BN * BPITCH_T * 2)         // 18432
#define BPITCH_N 136                         // 128 + 8 pad
#define BBYTES_N (BKK * BPITCH_N * 2)        // 17408

template <int MODE, bool BT>
__global__ void __launch_bounds__(256, 2)
gemm_mma(const h16* __restrict__ A, const h16* __restrict__ B,
         const float* __restrict__ bias,
         h16* __restrict__ C0, float* __restrict__ Cf,
         int lda, int ldb, int ldc, int K, float alpha,
         long long sA, long long sB, long long sC)
{
    constexpr int BBYTES  = BT ? BBYTES_T : BBYTES_N;
    constexpr int OFF_B   = ABYTES;
    constexpr int STAGE   = ABYTES + BBYTES;

    extern __shared__ char smem[];
    const u32 sb = smem_u32(smem);

    const int tid  = threadIdx.x;
    const int wid  = tid >> 5, lane = tid & 31;
    const int wm   = wid & 1, wn = wid >> 1;          // 2 x 4 warp grid
    const long long z = blockIdx.z;
    A += z * sA;
    B += z * sB;

    const int m0 = blockIdx.y * BM;
    const int n0 = blockIdx.x * BN;

    // ---- loader geometry (BK=64, 256 threads) ----
    const int ar0 = tid >> 2, ac = (tid & 3) * 16;
    const int nr0 = tid >> 4, nc = (tid & 15) * 8;

    auto load_stage = [&](int t) {
        const long long kb = (long long)t * BKK;
        const u32 st = sb + (u32)((t % 3) * STAGE);
#pragma unroll
        for (int i = 0; i < 2; i++) {
            const int r = ar0 + i * 64;
            const long long g = (long long)(m0 + r) * lda + kb + ac;
            const u32 d = st + (u32)(r * APITCH + ac) * 2;
            CP_ASYNC16(d,      A + g);
            CP_ASYNC16(d + 16, A + g + 8);
        }
        if (BT) {
#pragma unroll
            for (int i = 0; i < 2; i++) {
                const int r = ar0 + i * 64;
                const long long g = (long long)(n0 + r) * ldb + kb + ac;
                const u32 d = st + OFF_B + (u32)(r * BPITCH_T + ac) * 2;
                CP_ASYNC16(d,      B + g);
                CP_ASYNC16(d + 16, B + g + 8);
            }
        } else {
#pragma unroll
            for (int i = 0; i < 4; i++) {
                const int r = nr0 + i * 16;
                const long long g = (kb + r) * (long long)ldb + n0 + nc;
                const u32 d = st + OFF_B + (u32)(r * BPITCH_N + nc) * 2;
                CP_ASYNC16(d, B + g);
            }
        }
    };

    // ---- ldmatrix per-lane offsets ----
    const int a_lr = (lane & 7) + ((lane >> 3) & 1) * 8;
    const int a_lk = (lane >> 4) * 8;
    u32 a_off[4];
#pragma unroll
    for (int mt = 0; mt < 4; mt++)
        a_off[mt] = (u32)((wm * 64 + mt * 16 + a_lr) * APITCH + a_lk) * 2;

    const int l16 = lane & 15;
    u32 b_off[4];
    if (BT) {
        const int b_nr = l16 & 7, b_k = (l16 >> 3) * 8;
#pragma unroll
        for (int nt = 0; nt < 4; nt++)
            b_off[nt] = (u32)((wn * 32 + nt * 8 + b_nr) * BPITCH_T + b_k) * 2;
    } else {
        const int b_kr = l16;      // 16 k-rows
#pragma unroll
        for (int nt = 0; nt < 4; nt++)
            b_off[nt] = (u32)(b_kr * BPITCH_N + wn * 32 + nt * 8) * 2;
    }

    float acc[4][4][4];
#pragma unroll
    for (int i = 0; i < 4; i++)
#pragma unroll
        for (int j = 0; j < 4; j++)
#pragma unroll
            for (int v = 0; v < 4; v++) acc[i][j][v] = 0.0f;

    // single-buffered fragments (co-resident CTA hides the latency)
    u32 ah[4][4], bh[4][2];

    const int nst = K / BKK;

    load_stage(0); CP_COMMIT();
    load_stage(1); CP_COMMIT();

    for (int t = 0; t < nst; t++) {
        CP_WAIT1();
        __syncthreads();
        if (t + 2 < nst) load_stage(t + 2);
        CP_COMMIT();

        const u32 st  = sb + (u32)((t % 3) * STAGE);
        const u32 bAh = st;
        const u32 bBh = st + OFF_B;

#pragma unroll
        for (int kk = 0; kk < 4; kk++) {
            const u32 ak = (u32)(kk * 32);
            const u32 bk = BT ? (u32)(kk * 32) : (u32)(kk * 16 * BPITCH_N * 2);
#pragma unroll
            for (int mt = 0; mt < 4; mt++)
                ldsm_x4(ah[mt][0], ah[mt][1], ah[mt][2], ah[mt][3],
                        bAh + a_off[mt] + ak);
#pragma unroll
            for (int nt = 0; nt < 4; nt++) {
                if (BT) ldsm_x2(bh[nt][0], bh[nt][1], bBh + b_off[nt] + bk);
                else    ldsm_x2t(bh[nt][0], bh[nt][1], bBh + b_off[nt] + bk);
            }
#pragma unroll
            for (int mt = 0; mt < 4; mt++)
#pragma unroll
                for (int nt = 0; nt < 4; nt++)
                    mma_f16(acc[mt][nt], ah[mt], bh[nt]);
        }
    }

    // ---- epilogue ----
    const int gr = lane >> 2, gc = (lane & 3) * 2;
#pragma unroll
    for (int mt = 0; mt < 4; mt++) {
#pragma unroll
        for (int nt = 0; nt < 4; nt++) {
            const int m_ = m0 + wm * 64 + mt * 16 + gr;
            const int n_ = n0 + wn * 32 + nt * 8 + gc;
            const float* a4 = acc[mt][nt];
            if (MODE == 0) {
                const float b0 = bias[n_], b1 = bias[n_ + 1];
#pragma unroll
                for (int h = 0; h < 2; h++) {
                    const float v0 = a4[2 * h]     + b0;
                    const float v1 = a4[2 * h + 1] + b1;
                    const long long o = (long long)(m_ + 8 * h) * ldc + n_;
                    h16 hp[2] = { __half_as_ushort(__float2half_rn(v0)),
                                  __half_as_ushort(__float2half_rn(v1)) };
                    *(u32*)(C0 + o) = *(const u32*)hp;
                }
            } else {
                float* Cz = Cf + z * sC;
#pragma unroll
                for (int h = 0; h < 2; h++) {
                    const long long o = (long long)(m_ + 8 * h) * ldc + n_;
                    float2 v = make_float2(a4[2 * h] * alpha, a4[2 * h + 1] * alpha);
                    *(float2*)(Cz + o) = v;
                }
            }
        }
    }
}

// ---------------------------------------------------------------------------
// fp32 -> single fp16 conversion, both activations in one launch
// ---------------------------------------------------------------------------
__global__ void __launch_bounds__(256)
conv_f16_2(const float4* __restrict__ ina, h16* __restrict__ outa,
           const float4* __restrict__ inb, h16* __restrict__ outb)
{
    const bool second = blockIdx.x >= 16384;
    const long long i = ((long long)blockIdx.x - (second ? 16384 : 0)) * 256
                        + threadIdx.x;
    const float4 v = (second ? inb : ina)[i];
    h16 p[4] = { __half_as_ushort(__float2half_rn(v.x)),
                 __half_as_ushort(__float2half_rn(v.y)),
                 __half_as_ushort(__float2half_rn(v.z)),
                 __half_as_ushort(__float2half_rn(v.w)) };
    *(uint2*)&((second ? outb : outa)[i * 4]) = *(const uint2*)p;
}

// W [F=1024, H=1024] -> W^T single fp16 [H, F]; z selects which W
__global__ void wt_conv3(const float* __restrict__ W0, h16* __restrict__ T0,
                         const float* __restrict__ W1, h16* __restrict__ T1,
                         const float* __restrict__ W2, h16* __restrict__ T2)
{
    const float* W = (blockIdx.z == 0) ? W0 : (blockIdx.z == 1) ? W1 : W2;
    h16*         T = (blockIdx.z == 0) ? T0 : (blockIdx.z == 1) ? T1 : T2;
    __shared__ float ts[32][33];
    const int tx = threadIdx.x, ty = threadIdx.y;
    ts[ty][tx] = W[(long long)(blockIdx.y * 32 + ty) * 1024 + blockIdx.x * 32 + tx];
    __syncthreads();
    const float x = ts[tx][ty];
    const long long o = (long long)(blockIdx.x * 32 + ty) * 1024 + blockIdx.y * 32 + tx;
    T[o] = __half_as_ushort(__float2half_rn(x));
}

// ---------------------------------------------------------------------------
// Mask dtype detection (bool may arrive as u8/i32/f32)
// ---------------------------------------------------------------------------
__global__ void detect_mask_kernel(const unsigned char* __restrict__ m)
{
    __shared__ int bad_i32, bad_f32;
    if (threadIdx.x == 0) { bad_i32 = 0; bad_f32 = 0; }
    __syncthreads();
    const unsigned int* w = (const unsigned int*)m;
    for (int i = threadIdx.x; i < 2048; i += 256) {
        unsigned int x = w[i];
        if (x != 0u && x != 1u)          bad_i32 = 1;
        if (x != 0u && x != 0x3F800000u) bad_f32 = 1;
    }
    __syncthreads();
    if (threadIdx.x == 0)
        g_mask_mode = bad_i32 ? (bad_f32 ? 0 : 2) : 1;
}

// ---------------------------------------------------------------------------
// Masked softmax over rows of S (fp32) [B*TQ, 2048] -> P fp16
// ---------------------------------------------------------------------------
__global__ void __launch_bounds__(256)
softmax_kernel(const float* __restrict__ S, const void* __restrict__ maskv,
               h16* __restrict__ P)
{
    const int TK = 2048;
    const long long base = (long long)blockIdx.x * TK;
    const float* s = S + base;
    const int tid  = threadIdx.x;
    const int mode = g_mask_mode;

    float v[8];
    bool  keep[8];
#pragma unroll
    for (int i = 0; i < 8; i++) {
        const int idx = tid + i * 256;
        v[i] = s[idx];
        bool kp;
        if (mode == 1)      kp = ((const int*)maskv)[base + idx] != 0;
        else if (mode == 2) kp = ((const float*)maskv)[base + idx] != 0.0f;
        else                kp = ((const unsigned char*)maskv)[base + idx] != 0;
        keep[i] = kp;
    }

    float mx = -3.0e38f;
#pragma unroll
    for (int i = 0; i < 8; i++)
        if (keep[i]) mx = fmaxf(mx, v[i]);

    __shared__ float red[8];
#pragma unroll
    for (int o = 16; o > 0; o >>= 1)
        mx = fmaxf(mx, __shfl_xor_sync(0xffffffffu, mx, o));
    if ((tid & 31) == 0) red[tid >> 5] = mx;
    __syncthreads();
    float bm = red[0];
#pragma unroll
    for (int i = 1; i < 8; i++) bm = fmaxf(bm, red[i]);

    float sum = 0.0f;
#pragma unroll
    for (int i = 0; i < 8; i++) {
        const float e = keep[i] ? __expf(v[i] - bm) : 0.0f;
        v[i] = e;
        sum += e;
    }
#pragma unroll
    for (int o = 16; o > 0; o >>= 1)
        sum += __shfl_xor_sync(0xffffffffu, sum, o);
    __syncthreads();
    if ((tid & 31) == 0) red[tid >> 5] = sum;
    __syncthreads();
    float ts = 0.0f;
#pragma unroll
    for (int i = 0; i < 8; i++) ts += red[i];

    const float inv = 1.0f / ts;
#pragma unroll
    for (int i = 0; i < 8; i++)
        P[base + tid + i * 256] =
            __half_as_ushort(__float2half_rn(v[i] * inv));
}

// ---------------------------------------------------------------------------
// kernel_launch
// ---------------------------------------------------------------------------
extern "C" void kernel_launch(void* const* d_in, const int* in_sizes, int n_in,
                              void* d_out, int out_size)
{
    (void)in_sizes; (void)n_in; (void)out_size;

    const float* query = (const float*)d_in[0];
    const float* enc   = (const float*)d_in[1];
    const unsigned char* mask = (const unsigned char*)d_in[2];
    const float* Wq = (const float*)d_in[3];
    const float* bq = (const float*)d_in[4];
    const float* Wk = (const float*)d_in[5];
    const float* bk = (const float*)d_in[6];
    const float* Wv = (const float*)d_in[7];
    const float* bv = (const float*)d_in[8];
    float* out = (float*)d_out;

    h16 *Ef, *Xf, *Wqt, *Wkt, *Wvt;
    h16 *Q, *K, *V, *P;
    float* Sp;
    cudaGetSymbolAddress((void**)&Ef,  g_Ef);
    cudaGetSymbolAddress((void**)&Xf,  g_Xf);
    cudaGetSymbolAddress((void**)&Wqt, g_Wq);
    cudaGetSymbolAddress((void**)&Wkt, g_Wk);
    cudaGetSymbolAddress((void**)&Wvt, g_Wv);
    cudaGetSymbolAddress((void**)&Q,   g_Q);
    cudaGetSymbolAddress((void**)&K,   g_K);
    cudaGetSymbolAddress((void**)&V,   g_V);
    cudaGetSymbolAddress((void**)&P,   g_P);
    cudaGetSymbolAddress((void**)&Sp,  g_S);

    constexpr int SMEM_T = 3 * (ABYTES + BBYTES_T);   // 110592
    constexpr int SMEM_N = 3 * (ABYTES + BBYTES_N);   // 107520
    cudaFuncSetAttribute(gemm_mma<0, true>,
                         cudaFuncAttributeMaxDynamicSharedMemorySize, SMEM_T);
    cudaFuncSetAttribute(gemm_mma<2, true>,
                         cudaFuncAttributeMaxDynamicSharedMemorySize, SMEM_T);
    cudaFuncSetAttribute(gemm_mma<2, false>,
                         cudaFuncAttributeMaxDynamicSharedMemorySize, SMEM_N);

    const int T = 2048;

    // 1) convert activations to fp16 (one launch for enc + query)
    conv_f16_2<<<32768, 256>>>((const float4*)enc, Ef, (const float4*)query, Xf);

    // 2) transpose+convert all 3 weights (one launch)
    dim3 wtg(32, 32, 3), wtb(32, 32);
    wt_conv3<<<wtg, wtb>>>(Wq, Wqt, Wk, Wkt, Wv, Wvt);

    detect_mask_kernel<<<1, 256>>>(mask);

    // 3) projections: pure fp16, fp16 outputs
    dim3 gp(1024 / BN, 16384 / BM, 1);
    gemm_mma<0, true><<<gp, 256, SMEM_T>>>(Ef, Wkt, bk,
        K, nullptr, 1024, 1024, 1024, 1024, 1.0f, 0, 0, 0);
    gemm_mma<0, true><<<gp, 256, SMEM_T>>>(Ef, Wvt, bv,
        V, nullptr, 1024, 1024, 1024, 1024, 1.0f, 0, 0, 0);
    gemm_mma<0, true><<<gp, 256, SMEM_T>>>(Xf, Wqt, bq,
        Q, nullptr, 1024, 1024, 1024, 1024, 1.0f, 0, 0, 0);

    // 4) scores: S = (Q K^T) / 32, fp32 out
    dim3 gs(T / BN, T / BM, 8);
    gemm_mma<2, true><<<gs, 256, SMEM_T>>>(Q, K, nullptr,
        nullptr, Sp, 1024, 1024, 2048, 1024, 0.03125f,
        2048LL * 1024, 2048LL * 1024, 2048LL * 2048);

    // 5) masked softmax (fp32 in, fp16 out)
    softmax_kernel<<<8 * T, 256>>>(Sp, (const void*)mask, P);

    // 6) output: O = P V   (V NN layout, ldmatrix.trans), fp32 out
    dim3 go(1024 / BN, T / BM, 8);
    gemm_mma<2, false><<<go, 256, SMEM_N>>>(P, V, nullptr,
        nullptr, out, 2048, 1024, 1024, 2048, 1.0f,
        2048LL * 2048, 2048LL * 1024, 2048LL * 1024);
}

// round 15
// speedup vs baseline: 1.8191x; 1.0026x over previous
#include <cuda_runtime.h>
#include <cuda_fp16.h>

typedef unsigned short h16;    // opaque 16-bit payload (fp16 bits)
typedef unsigned int u32;
typedef unsigned long long u64;

// ---------------------------------------------------------------------------
// Problem constants: B=8, TQ=TK=2048, F=1024, H=1024
// ---------------------------------------------------------------------------
#define MTOT (16384LL * 1024)

static __device__ h16   g_Ef[MTOT];                           // encoder fp16
static __device__ h16   g_Xf[MTOT];                           // query fp16
static __device__ h16   g_Wq[1024*1024];                      // W^T fp16
static __device__ h16   g_Wk[1024*1024];
static __device__ h16   g_Wv[1024*1024];
static __device__ h16   g_Q[MTOT];                            // fp16
static __device__ h16   g_K[MTOT];                            // fp16
static __device__ h16   g_V[MTOT];                            // fp16 [b*2048+t][1024]
static __device__ float g_S[8LL * 2048 * 2048];               // scores fp32
static __device__ h16   g_P[8LL * 2048 * 2048];               // probs fp16
static __device__ int   g_mask_mode;

// ---------------------------------------------------------------------------
// PTX helpers (sm_80-era; legal under generic compute_103 target)
// ---------------------------------------------------------------------------
__device__ __forceinline__ u32 smem_u32(const void* p) {
    u32 a;
    asm("{ .reg .u64 t; cvta.to.shared.u64 t, %1; cvt.u32.u64 %0, t; }"
        : "=r"(a) : "l"(p));
    return a;
}
#define CP_ASYNC16(dst, src) \
    asm volatile("cp.async.cg.shared.global [%0], [%1], 16;" \
                 :: "r"(dst), "l"(src) : "memory")
#define CP_COMMIT() asm volatile("cp.async.commit_group;" ::: "memory")
#define CP_WAIT1()  asm volatile("cp.async.wait_group 1;" ::: "memory")

__device__ __forceinline__ void ldsm_x4(u32& r0, u32& r1, u32& r2, u32& r3, u32 a) {
    asm volatile("ldmatrix.sync.aligned.m8n8.x4.shared.b16 {%0,%1,%2,%3}, [%4];"
                 : "=r"(r0), "=r"(r1), "=r"(r2), "=r"(r3) : "r"(a));
}
__device__ __forceinline__ void ldsm_x4t(u32& r0, u32& r1, u32& r2, u32& r3, u32 a) {
    asm volatile("ldmatrix.sync.aligned.m8n8.x4.trans.shared.b16 {%0,%1,%2,%3}, [%4];"
                 : "=r"(r0), "=r"(r1), "=r"(r2), "=r"(r3) : "r"(a));
}
__device__ __forceinline__ void mma_f16(float* c, const u32* a, const u32* b) {
    asm volatile(
        "mma.sync.aligned.m16n8k16.row.col.f32.f16.f16.f32 "
        "{%0,%1,%2,%3}, {%4,%5,%6,%7}, {%8,%9}, {%0,%1,%2,%3};"
        : "+f"(c[0]), "+f"(c[1]), "+f"(c[2]), "+f"(c[3])
        : "r"(a[0]), "r"(a[1]), "r"(a[2]), "r"(a[3]), "r"(b[0]), "r"(b[1]));
}

// ---------------------------------------------------------------------------
// GEMM: D[m,n] = sum_k A[m,k]*B'[k,n]   (pure fp16, 1 MMA per k-tile)
//   BT=true : B stored [N][K] -> ldmatrix; BT=false: B [K][N] -> ldmatrix.trans
//   MODE 0: fp16 out + bias;  MODE 2: fp32 out * alpha
// CTA tile 128x128, BK=64, 3-stage cp.async pipeline, 256 threads (8 warps
// 2x4), TWO CTAs per SM. B fragments loaded with ldmatrix.x4 (2 nt tiles per
// instruction): 6 LDSM per kk instead of 8.
// ---------------------------------------------------------------------------
#define BM 128
#define BN 128
#define BKK 64
#define APITCH 72                            // 64 + 8 pad (16b units)
#define ABYTES (BM * APITCH * 2)             // 18432
#define BPITCH_T 72
#define BBYTES_T (BN * BPITCH_T * 2)         // 18432
#define BPITCH_N 136                         // 128 + 8 pad
#define BBYTES_N (BKK * BPITCH_N * 2)        // 17408

template <int MODE, bool BT>
__global__ void __launch_bounds__(256, 2)
gemm_mma(const h16* __restrict__ A, const h16* __restrict__ B,
         const float* __restrict__ bias,
         h16* __restrict__ C0, float* __restrict__ Cf,
         int lda, int ldb, int ldc, int K, float alpha,
         long long sA, long long sB, long long sC)
{
    constexpr int BBYTES  = BT ? BBYTES_T : BBYTES_N;
    constexpr int OFF_B   = ABYTES;
    constexpr int STAGE   = ABYTES + BBYTES;

    extern __shared__ char smem[];
    const u32 sb = smem_u32(smem);

    const int tid  = threadIdx.x;
    const int wid  = tid >> 5, lane = tid & 31;
    const int wm   = wid & 1, wn = wid >> 1;          // 2 x 4 warp grid
    const long long z = blockIdx.z;
    A += z * sA;
    B += z * sB;

    const int m0 = blockIdx.y * BM;
    const int n0 = blockIdx.x * BN;

    // ---- loader geometry (BK=64, 256 threads) ----
    const int ar0 = tid >> 2, ac = (tid & 3) * 16;
    const int nr0 = tid >> 4, nc = (tid & 15) * 8;

    auto load_stage = [&](int t) {
        const long long kb = (long long)t * BKK;
        const u32 st = sb + (u32)((t % 3) * STAGE);
#pragma unroll
        for (int i = 0; i < 2; i++) {
            const int r = ar0 + i * 64;
            const long long g = (long long)(m0 + r) * lda + kb + ac;
            const u32 d = st + (u32)(r * APITCH + ac) * 2;
            CP_ASYNC16(d,      A + g);
            CP_ASYNC16(d + 16, A + g + 8);
        }
        if (BT) {
#pragma unroll
            for (int i = 0; i < 2; i++) {
                const int r = ar0 + i * 64;
                const long long g = (long long)(n0 + r) * ldb + kb + ac;
                const u32 d = st + OFF_B + (u32)(r * BPITCH_T + ac) * 2;
                CP_ASYNC16(d,      B + g);
                CP_ASYNC16(d + 16, B + g + 8);
            }
        } else {
#pragma unroll
            for (int i = 0; i < 4; i++) {
                const int r = nr0 + i * 16;
                const long long g = (kb + r) * (long long)ldb + n0 + nc;
                const u32 d = st + OFF_B + (u32)(r * BPITCH_N + nc) * 2;
                CP_ASYNC16(d, B + g);
            }
        }
    };

    // ---- ldmatrix per-lane offsets ----
    const int a_lr = (lane & 7) + ((lane >> 3) & 1) * 8;
    const int a_lk = (lane >> 4) * 8;
    u32 a_off[4];
#pragma unroll
    for (int mt = 0; mt < 4; mt++)
        a_off[mt] = (u32)((wm * 64 + mt * 16 + a_lr) * APITCH + a_lk) * 2;

    // B x4 offsets: one per nt-PAIR. Lane groups (lane>>3):
    //   g0 -> (nt, k0-7), g1 -> (nt, k8-15), g2 -> (nt+1, k0-7), g3 -> (nt+1, k8-15)
    u32 b_off4[2];
    {
        const int l7 = lane & 7;
        const int kh = (lane >> 3) & 1;      // k-half select
        const int nh = (lane >> 4) & 1;      // nt-within-pair select
        if (BT) {
#pragma unroll
            for (int ntp = 0; ntp < 2; ntp++)
                b_off4[ntp] = (u32)(((wn * 32 + ntp * 16 + nh * 8 + l7) * BPITCH_T
                                     + kh * 8) * 2);
        } else {
#pragma unroll
            for (int ntp = 0; ntp < 2; ntp++)
                b_off4[ntp] = (u32)(((kh * 8 + l7) * BPITCH_N
                                     + wn * 32 + ntp * 16 + nh * 8) * 2);
        }
    }

    float acc[4][4][4];
#pragma unroll
    for (int i = 0; i < 4; i++)
#pragma unroll
        for (int j = 0; j < 4; j++)
#pragma unroll
            for (int v = 0; v < 4; v++) acc[i][j][v] = 0.0f;

    // single-buffered fragments (co-resident CTA hides the latency)
    u32 ah[4][4], bh[4][2];

    const int nst = K / BKK;

    load_stage(0); CP_COMMIT();
    load_stage(1); CP_COMMIT();

    for (int t = 0; t < nst; t++) {
        CP_WAIT1();
        __syncthreads();
        if (t + 2 < nst) load_stage(t + 2);
        CP_COMMIT();

        const u32 st  = sb + (u32)((t % 3) * STAGE);
        const u32 bAh = st;
        const u32 bBh = st + OFF_B;

#pragma unroll
        for (int kk = 0; kk < 4; kk++) {
            const u32 ak = (u32)(kk * 32);
            const u32 bk = BT ? (u32)(kk * 32) : (u32)(kk * 16 * BPITCH_N * 2);
#pragma unroll
            for (int ntp = 0; ntp < 2; ntp++) {
                if (BT)
                    ldsm_x4(bh[2*ntp][0], bh[2*ntp][1],
                            bh[2*ntp+1][0], bh[2*ntp+1][1],
                            bBh + b_off4[ntp] + bk);
                else
                    ldsm_x4t(bh[2*ntp][0], bh[2*ntp][1],
                             bh[2*ntp+1][0], bh[2*ntp+1][1],
                             bBh + b_off4[ntp] + bk);
            }
#pragma unroll
            for (int mt = 0; mt < 4; mt++)
                ldsm_x4(ah[mt][0], ah[mt][1], ah[mt][2], ah[mt][3],
                        bAh + a_off[mt] + ak);
#pragma unroll
            for (int mt = 0; mt < 4; mt++)
#pragma unroll
                for (int nt = 0; nt < 4; nt++)
                    mma_f16(acc[mt][nt], ah[mt], bh[nt]);
        }
    }

    // ---- epilogue ----
    const int gr = lane >> 2, gc = (lane & 3) * 2;
#pragma unroll
    for (int mt = 0; mt < 4; mt++) {
#pragma unroll
        for (int nt = 0; nt < 4; nt++) {
            const int m_ = m0 + wm * 64 + mt * 16 + gr;
            const int n_ = n0 + wn * 32 + nt * 8 + gc;
            const float* a4 = acc[mt][nt];
            if (MODE == 0) {
                const float b0 = bias[n_], b1 = bias[n_ + 1];
#pragma unroll
                for (int h = 0; h < 2; h++) {
                    const float v0 = a4[2 * h]     + b0;
                    const float v1 = a4[2 * h + 1] + b1;
                    const long long o = (long long)(m_ + 8 * h) * ldc + n_;
                    h16 hp[2] = { __half_as_ushort(__float2half_rn(v0)),
                                  __half_as_ushort(__float2half_rn(v1)) };
                    *(u32*)(C0 + o) = *(const u32*)hp;
                }
            } else {
                float* Cz = Cf + z * sC;
#pragma unroll
                for (int h = 0; h < 2; h++) {
                    const long long o = (long long)(m_ + 8 * h) * ldc + n_;
                    float2 v = make_float2(a4[2 * h] * alpha, a4[2 * h + 1] * alpha);
                    *(float2*)(Cz + o) = v;
                }
            }
        }
    }
}

// ---------------------------------------------------------------------------
// fp32 -> single fp16 conversion, both activations in one launch
// ---------------------------------------------------------------------------
__global__ void __launch_bounds__(256)
conv_f16_2(const float4* __restrict__ ina, h16* __restrict__ outa,
           const float4* __restrict__ inb, h16* __restrict__ outb)
{
    const bool second = blockIdx.x >= 16384;
    const long long i = ((long long)blockIdx.x - (second ? 16384 : 0)) * 256
                        + threadIdx.x;
    const float4 v = (second ? inb : ina)[i];
    h16 p[4] = { __half_as_ushort(__float2half_rn(v.x)),
                 __half_as_ushort(__float2half_rn(v.y)),
                 __half_as_ushort(__float2half_rn(v.z)),
                 __half_as_ushort(__float2half_rn(v.w)) };
    *(uint2*)&((second ? outb : outa)[i * 4]) = *(const uint2*)p;
}

// W [F=1024, H=1024] -> W^T single fp16 [H, F]; z selects which W
__global__ void wt_conv3(const float* __restrict__ W0, h16* __restrict__ T0,
                         const float* __restrict__ W1, h16* __restrict__ T1,
                         const float* __restrict__ W2, h16* __restrict__ T2)
{
    const float* W = (blockIdx.z == 0) ? W0 : (blockIdx.z == 1) ? W1 : W2;
    h16*         T = (blockIdx.z == 0) ? T0 : (blockIdx.z == 1) ? T1 : T2;
    __shared__ float ts[32][33];
    const int tx = threadIdx.x, ty = threadIdx.y;
    ts[ty][tx] = W[(long long)(blockIdx.y * 32 + ty) * 1024 + blockIdx.x * 32 + tx];
    __syncthreads();
    const float x = ts[tx][ty];
    const long long o = (long long)(blockIdx.x * 32 + ty) * 1024 + blockIdx.y * 32 + tx;
    T[o] = __half_as_ushort(__float2half_rn(x));
}

// ---------------------------------------------------------------------------
// Mask dtype detection (bool may arrive as u8/i32/f32)
// ---------------------------------------------------------------------------
__global__ void detect_mask_kernel(const unsigned char* __restrict__ m)
{
    __shared__ int bad_i32, bad_f32;
    if (threadIdx.x == 0) { bad_i32 = 0; bad_f32 = 0; }
    __syncthreads();
    const unsigned int* w = (const unsigned int*)m;
    for (int i = threadIdx.x; i < 2048; i += 256) {
        unsigned int x = w[i];
        if (x != 0u && x != 1u)          bad_i32 = 1;
        if (x != 0u && x != 0x3F800000u) bad_f32 = 1;
    }
    __syncthreads();
    if (threadIdx.x == 0)
        g_mask_mode = bad_i32 ? (bad_f32 ? 0 : 2) : 1;
}

// ---------------------------------------------------------------------------
// Masked softmax over rows of S (fp32) [B*TQ, 2048] -> P fp16
// ---------------------------------------------------------------------------
__global__ void __launch_bounds__(256)
softmax_kernel(const float* __restrict__ S, const void* __restrict__ maskv,
               h16* __restrict__ P)
{
    const int TK = 2048;
    const long long base = (long long)blockIdx.x * TK;
    const float* s = S + base;
    const int tid  = threadIdx.x;
    const int mode = g_mask_mode;

    float v[8];
    bool  keep[8];
#pragma unroll
    for (int i = 0; i < 8; i++) {
        const int idx = tid + i * 256;
        v[i] = s[idx];
        bool kp;
        if (mode == 1)      kp = ((const int*)maskv)[base + idx] != 0;
        else if (mode == 2) kp = ((const float*)maskv)[base + idx] != 0.0f;
        else                kp = ((const unsigned char*)maskv)[base + idx] != 0;
        keep[i] = kp;
    }

    float mx = -3.0e38f;
#pragma unroll
    for (int i = 0; i < 8; i++)
        if (keep[i]) mx = fmaxf(mx, v[i]);

    __shared__ float red[8];
#pragma unroll
    for (int o = 16; o > 0; o >>= 1)
        mx = fmaxf(mx, __shfl_xor_sync(0xffffffffu, mx, o));
    if ((tid & 31) == 0) red[tid >> 5] = mx;
    __syncthreads();
    float bm = red[0];
#pragma unroll
    for (int i = 1; i < 8; i++) bm = fmaxf(bm, red[i]);

    float sum = 0.0f;
#pragma unroll
    for (int i = 0; i < 8; i++) {
        const float e = keep[i] ? __expf(v[i] - bm) : 0.0f;
        v[i] = e;
        sum += e;
    }
#pragma unroll
    for (int o = 16; o > 0; o >>= 1)
        sum += __shfl_xor_sync(0xffffffffu, sum, o);
    __syncthreads();
    if ((tid & 31) == 0) red[tid >> 5] = sum;
    __syncthreads();
    float ts = 0.0f;
#pragma unroll
    for (int i = 0; i < 8; i++) ts += red[i];

    const float inv = 1.0f / ts;
#pragma unroll
    for (int i = 0; i < 8; i++)
        P[base + tid + i * 256] =
            __half_as_ushort(__float2half_rn(v[i] * inv));
}

// ---------------------------------------------------------------------------
// kernel_launch
// ---------------------------------------------------------------------------
extern "C" void kernel_launch(void* const* d_in, const int* in_sizes, int n_in,
                              void* d_out, int out_size)
{
    (void)in_sizes; (void)n_in; (void)out_size;

    const float* query = (const float*)d_in[0];
    const float* enc   = (const float*)d_in[1];
    const unsigned char* mask = (const unsigned char*)d_in[2];
    const float* Wq = (const float*)d_in[3];
    const float* bq = (const float*)d_in[4];
    const float* Wk = (const float*)d_in[5];
    const float* bk = (const float*)d_in[6];
    const float* Wv = (const float*)d_in[7];
    const float* bv = (const float*)d_in[8];
    float* out = (float*)d_out;

    h16 *Ef, *Xf, *Wqt, *Wkt, *Wvt;
    h16 *Q, *K, *V, *P;
    float* Sp;
    cudaGetSymbolAddress((void**)&Ef,  g_Ef);
    cudaGetSymbolAddress((void**)&Xf,  g_Xf);
    cudaGetSymbolAddress((void**)&Wqt, g_Wq);
    cudaGetSymbolAddress((void**)&Wkt, g_Wk);
    cudaGetSymbolAddress((void**)&Wvt, g_Wv);
    cudaGetSymbolAddress((void**)&Q,   g_Q);
    cudaGetSymbolAddress((void**)&K,   g_K);
    cudaGetSymbolAddress((void**)&V,   g_V);
    cudaGetSymbolAddress((void**)&P,   g_P);
    cudaGetSymbolAddress((void**)&Sp,  g_S);

    constexpr int SMEM_T = 3 * (ABYTES + BBYTES_T);   // 110592
    constexpr int SMEM_N = 3 * (ABYTES + BBYTES_N);   // 107520
    cudaFuncSetAttribute(gemm_mma<0, true>,
                         cudaFuncAttributeMaxDynamicSharedMemorySize, SMEM_T);
    cudaFuncSetAttribute(gemm_mma<2, true>,
                         cudaFuncAttributeMaxDynamicSharedMemorySize, SMEM_T);
    cudaFuncSetAttribute(gemm_mma<2, false>,
                         cudaFuncAttributeMaxDynamicSharedMemorySize, SMEM_N);

    const int T = 2048;

    // 1) convert activations to fp16 (one launch for enc + query)
    conv_f16_2<<<32768, 256>>>((const float4*)enc, Ef, (const float4*)query, Xf);

    // 2) transpose+convert all 3 weights (one launch)
    dim3 wtg(32, 32, 3), wtb(32, 32);
    wt_conv3<<<wtg, wtb>>>(Wq, Wqt, Wk, Wkt, Wv, Wvt);

    detect_mask_kernel<<<1, 256>>>(mask);

    // 3) projections: pure fp16, fp16 outputs
    dim3 gp(1024 / BN, 16384 / BM, 1);
    gemm_mma<0, true><<<gp, 256, SMEM_T>>>(Ef, Wkt, bk,
        K, nullptr, 1024, 1024, 1024, 1024, 1.0f, 0, 0, 0);
    gemm_mma<0, true><<<gp, 256, SMEM_T>>>(Ef, Wvt, bv,
        V, nullptr, 1024, 1024, 1024, 1024, 1.0f, 0, 0, 0);
    gemm_mma<0, true><<<gp, 256, SMEM_T>>>(Xf, Wqt, bq,
        Q, nullptr, 1024, 1024, 1024, 1024, 1.0f, 0, 0, 0);

    // 4) scores: S = (Q K^T) / 32, fp32 out
    dim3 gs(T / BN, T / BM, 8);
    gemm_mma<2, true><<<gs, 256, SMEM_T>>>(Q, K, nullptr,
        nullptr, Sp, 1024, 1024, 2048, 1024, 0.03125f,
        2048LL * 1024, 2048LL * 1024, 2048LL * 2048);

    // 5) masked softmax (fp32 in, fp16 out)
    softmax_kernel<<<8 * T, 256>>>(Sp, (const void*)mask, P);

    // 6) output: O = P V   (V NN layout, ldmatrix.trans), fp32 out
    dim3 go(1024 / BN, T / BM, 8);
    gemm_mma<2, false><<<go, 256, SMEM_N>>>(P, V, nullptr,
        nullptr, out, 2048, 1024, 1024, 2048, 1.0f,
        2048LL * 2048, 2048LL * 1024, 2048LL * 1024);
}

// round 16
// speedup vs baseline: 1.8416x; 1.0123x over previous
#include <cuda_runtime.h>
#include <cuda_fp16.h>

typedef unsigned short h16;    // opaque 16-bit payload (fp16 bits)
typedef unsigned int u32;
typedef unsigned long long u64;

// ---------------------------------------------------------------------------
// Problem constants: B=8, TQ=TK=2048, F=1024, H=1024
// ---------------------------------------------------------------------------
#define MTOT (16384LL * 1024)

static __device__ h16   g_Ef[MTOT];                           // encoder fp16
static __device__ h16   g_Xf[MTOT];                           // query fp16
static __device__ h16   g_Wq[1024*1024];                      // W^T fp16
static __device__ h16   g_Wk[1024*1024];
static __device__ h16   g_Wv[1024*1024];
static __device__ h16   g_Q[MTOT];                            // fp16
static __device__ h16   g_K[MTOT];                            // fp16
static __device__ h16   g_V[MTOT];                            // fp16 [b*2048+t][1024]
static __device__ h16   g_S[8LL * 2048 * 2048];               // scores fp16
static __device__ h16   g_P[8LL * 2048 * 2048];               // probs fp16
static __device__ int   g_mask_mode;

// ---------------------------------------------------------------------------
// PTX helpers (sm_80-era; legal under generic compute_103 target)
// ---------------------------------------------------------------------------
__device__ __forceinline__ u32 smem_u32(const void* p) {
    u32 a;
    asm("{ .reg .u64 t; cvta.to.shared.u64 t, %1; cvt.u32.u64 %0, t; }"
        : "=r"(a) : "l"(p));
    return a;
}
#define CP_ASYNC16(dst, src) \
    asm volatile("cp.async.cg.shared.global [%0], [%1], 16;" \
                 :: "r"(dst), "l"(src) : "memory")
#define CP_COMMIT() asm volatile("cp.async.commit_group;" ::: "memory")
#define CP_WAIT1()  asm volatile("cp.async.wait_group 1;" ::: "memory")

__device__ __forceinline__ void ldsm_x4(u32& r0, u32& r1, u32& r2, u32& r3, u32 a) {
    asm volatile("ldmatrix.sync.aligned.m8n8.x4.shared.b16 {%0,%1,%2,%3}, [%4];"
                 : "=r"(r0), "=r"(r1), "=r"(r2), "=r"(r3) : "r"(a));
}
__device__ __forceinline__ void ldsm_x4t(u32& r0, u32& r1, u32& r2, u32& r3, u32 a) {
    asm volatile("ldmatrix.sync.aligned.m8n8.x4.trans.shared.b16 {%0,%1,%2,%3}, [%4];"
                 : "=r"(r0), "=r"(r1), "=r"(r2), "=r"(r3) : "r"(a));
}
__device__ __forceinline__ void mma_f16(float* c, const u32* a, const u32* b) {
    asm volatile(
        "mma.sync.aligned.m16n8k16.row.col.f32.f16.f16.f32 "
        "{%0,%1,%2,%3}, {%4,%5,%6,%7}, {%8,%9}, {%0,%1,%2,%3};"
        : "+f"(c[0]), "+f"(c[1]), "+f"(c[2]), "+f"(c[3])
        : "r"(a[0]), "r"(a[1]), "r"(a[2]), "r"(a[3]), "r"(b[0]), "r"(b[1]));
}

// ---------------------------------------------------------------------------
// GEMM: D[m,n] = sum_k A[m,k]*B'[k,n]   (pure fp16, 1 MMA per k-tile)
//   BT=true : B stored [N][K] -> ldmatrix; BT=false: B [K][N] -> ldmatrix.trans
//   MODE 0: fp16 out + bias;  MODE 2: fp32 out * alpha;  MODE 3: fp16 out * alpha
// CTA tile 128x128, BK=64, 3-stage cp.async pipeline, 256 threads (8 warps
// 2x4), TWO CTAs per SM, x4 B-fragment loads (6 LDSM per kk).
// ---------------------------------------------------------------------------
#define BM 128
#define BN 128
#define BKK 64
#define APITCH 72                            // 64 + 8 pad (16b units)
#define ABYTES (BM * APITCH * 2)             // 18432
#define BPITCH_T 72
#define BBYTES_T (BN * BPITCH_T * 2)         // 18432
#define BPITCH_N 136                         // 128 + 8 pad
#define BBYTES_N (BKK * BPITCH_N * 2)        // 17408

template <int MODE, bool BT>
__global__ void __launch_bounds__(256, 2)
gemm_mma(const h16* __restrict__ A, const h16* __restrict__ B,
         const float* __restrict__ bias,
         h16* __restrict__ C0, float* __restrict__ Cf,
         int lda, int ldb, int ldc, int K, float alpha,
         long long sA, long long sB, long long sC)
{
    constexpr int BBYTES  = BT ? BBYTES_T : BBYTES_N;
    constexpr int OFF_B   = ABYTES;
    constexpr int STAGE   = ABYTES + BBYTES;

    extern __shared__ char smem[];
    const u32 sb = smem_u32(smem);

    const int tid  = threadIdx.x;
    const int wid  = tid >> 5, lane = tid & 31;
    const int wm   = wid & 1, wn = wid >> 1;          // 2 x 4 warp grid
    const long long z = blockIdx.z;
    A += z * sA;
    B += z * sB;

    const int m0 = blockIdx.y * BM;
    const int n0 = blockIdx.x * BN;

    // ---- loader geometry (BK=64, 256 threads) ----
    const int ar0 = tid >> 2, ac = (tid & 3) * 16;
    const int nr0 = tid >> 4, nc = (tid & 15) * 8;

    auto load_stage = [&](int t) {
        const long long kb = (long long)t * BKK;
        const u32 st = sb + (u32)((t % 3) * STAGE);
#pragma unroll
        for (int i = 0; i < 2; i++) {
            const int r = ar0 + i * 64;
            const long long g = (long long)(m0 + r) * lda + kb + ac;
            const u32 d = st + (u32)(r * APITCH + ac) * 2;
            CP_ASYNC16(d,      A + g);
            CP_ASYNC16(d + 16, A + g + 8);
        }
        if (BT) {
#pragma unroll
            for (int i = 0; i < 2; i++) {
                const int r = ar0 + i * 64;
                const long long g = (long long)(n0 + r) * ldb + kb + ac;
                const u32 d = st + OFF_B + (u32)(r * BPITCH_T + ac) * 2;
                CP_ASYNC16(d,      B + g);
                CP_ASYNC16(d + 16, B + g + 8);
            }
        } else {
#pragma unroll
            for (int i = 0; i < 4; i++) {
                const int r = nr0 + i * 16;
                const long long g = (kb + r) * (long long)ldb + n0 + nc;
                const u32 d = st + OFF_B + (u32)(r * BPITCH_N + nc) * 2;
                CP_ASYNC16(d, B + g);
            }
        }
    };

    // ---- ldmatrix per-lane offsets ----
    const int a_lr = (lane & 7) + ((lane >> 3) & 1) * 8;
    const int a_lk = (lane >> 4) * 8;
    u32 a_off[4];
#pragma unroll
    for (int mt = 0; mt < 4; mt++)
        a_off[mt] = (u32)((wm * 64 + mt * 16 + a_lr) * APITCH + a_lk) * 2;

    // B x4 offsets: one per nt-PAIR. Lane groups (lane>>3):
    //   g0 -> (nt, k0-7), g1 -> (nt, k8-15), g2 -> (nt+1, k0-7), g3 -> (nt+1, k8-15)
    u32 b_off4[2];
    {
        const int l7 = lane & 7;
        const int kh = (lane >> 3) & 1;      // k-half select
        const int nh = (lane >> 4) & 1;      // nt-within-pair select
        if (BT) {
#pragma unroll
            for (int ntp = 0; ntp < 2; ntp++)
                b_off4[ntp] = (u32)(((wn * 32 + ntp * 16 + nh * 8 + l7) * BPITCH_T
                                     + kh * 8) * 2);
        } else {
#pragma unroll
            for (int ntp = 0; ntp < 2; ntp++)
                b_off4[ntp] = (u32)(((kh * 8 + l7) * BPITCH_N
                                     + wn * 32 + ntp * 16 + nh * 8) * 2);
        }
    }

    float acc[4][4][4];
#pragma unroll
    for (int i = 0; i < 4; i++)
#pragma unroll
        for (int j = 0; j < 4; j++)
#pragma unroll
            for (int v = 0; v < 4; v++) acc[i][j][v] = 0.0f;

    // single-buffered fragments (co-resident CTA hides the latency)
    u32 ah[4][4], bh[4][2];

    const int nst = K / BKK;

    load_stage(0); CP_COMMIT();
    load_stage(1); CP_COMMIT();

    for (int t = 0; t < nst; t++) {
        CP_WAIT1();
        __syncthreads();
        if (t + 2 < nst) load_stage(t + 2);
        CP_COMMIT();

        const u32 st  = sb + (u32)((t % 3) * STAGE);
        const u32 bAh = st;
        const u32 bBh = st + OFF_B;

#pragma unroll
        for (int kk = 0; kk < 4; kk++) {
            const u32 ak = (u32)(kk * 32);
            const u32 bk = BT ? (u32)(kk * 32) : (u32)(kk * 16 * BPITCH_N * 2);
#pragma unroll
            for (int ntp = 0; ntp < 2; ntp++) {
                if (BT)
                    ldsm_x4(bh[2*ntp][0], bh[2*ntp][1],
                            bh[2*ntp+1][0], bh[2*ntp+1][1],
                            bBh + b_off4[ntp] + bk);
                else
                    ldsm_x4t(bh[2*ntp][0], bh[2*ntp][1],
                             bh[2*ntp+1][0], bh[2*ntp+1][1],
                             bBh + b_off4[ntp] + bk);
            }
#pragma unroll
            for (int mt = 0; mt < 4; mt++)
                ldsm_x4(ah[mt][0], ah[mt][1], ah[mt][2], ah[mt][3],
                        bAh + a_off[mt] + ak);
#pragma unroll
            for (int mt = 0; mt < 4; mt++)
#pragma unroll
                for (int nt = 0; nt < 4; nt++)
                    mma_f16(acc[mt][nt], ah[mt], bh[nt]);
        }
    }

    // ---- epilogue ----
    const int gr = lane >> 2, gc = (lane & 3) * 2;
#pragma unroll
    for (int mt = 0; mt < 4; mt++) {
#pragma unroll
        for (int nt = 0; nt < 4; nt++) {
            const int m_ = m0 + wm * 64 + mt * 16 + gr;
            const int n_ = n0 + wn * 32 + nt * 8 + gc;
            const float* a4 = acc[mt][nt];
            if (MODE == 0) {
                const float b0 = bias[n_], b1 = bias[n_ + 1];
#pragma unroll
                for (int h = 0; h < 2; h++) {
                    const float v0 = a4[2 * h]     + b0;
                    const float v1 = a4[2 * h + 1] + b1;
                    const long long o = (long long)(m_ + 8 * h) * ldc + n_;
                    h16 hp[2] = { __half_as_ushort(__float2half_rn(v0)),
                                  __half_as_ushort(__float2half_rn(v1)) };
                    *(u32*)(C0 + o) = *(const u32*)hp;
                }
            } else if (MODE == 3) {
                h16* Cz = C0 + z * sC;
#pragma unroll
                for (int h = 0; h < 2; h++) {
                    const long long o = (long long)(m_ + 8 * h) * ldc + n_;
                    h16 hp[2] = { __half_as_ushort(__float2half_rn(a4[2*h]   * alpha)),
                                  __half_as_ushort(__float2half_rn(a4[2*h+1] * alpha)) };
                    *(u32*)(Cz + o) = *(const u32*)hp;
                }
            } else {
                float* Cz = Cf + z * sC;
#pragma unroll
                for (int h = 0; h < 2; h++) {
                    const long long o = (long long)(m_ + 8 * h) * ldc + n_;
                    float2 v = make_float2(a4[2 * h] * alpha, a4[2 * h + 1] * alpha);
                    *(float2*)(Cz + o) = v;
                }
            }
        }
    }
}

// ---------------------------------------------------------------------------
// fp32 -> single fp16 conversion, both activations in one launch
// ---------------------------------------------------------------------------
__global__ void __launch_bounds__(256)
conv_f16_2(const float4* __restrict__ ina, h16* __restrict__ outa,
           const float4* __restrict__ inb, h16* __restrict__ outb)
{
    const bool second = blockIdx.x >= 16384;
    const long long i = ((long long)blockIdx.x - (second ? 16384 : 0)) * 256
                        + threadIdx.x;
    const float4 v = (second ? inb : ina)[i];
    h16 p[4] = { __half_as_ushort(__float2half_rn(v.x)),
                 __half_as_ushort(__float2half_rn(v.y)),
                 __half_as_ushort(__float2half_rn(v.z)),
                 __half_as_ushort(__float2half_rn(v.w)) };
    *(uint2*)&((second ? outb : outa)[i * 4]) = *(const uint2*)p;
}

// W [F=1024, H=1024] -> W^T single fp16 [H, F]; z selects which W
__global__ void wt_conv3(const float* __restrict__ W0, h16* __restrict__ T0,
                         const float* __restrict__ W1, h16* __restrict__ T1,
                         const float* __restrict__ W2, h16* __restrict__ T2)
{
    const float* W = (blockIdx.z == 0) ? W0 : (blockIdx.z == 1) ? W1 : W2;
    h16*         T = (blockIdx.z == 0) ? T0 : (blockIdx.z == 1) ? T1 : T2;
    __shared__ float ts[32][33];
    const int tx = threadIdx.x, ty = threadIdx.y;
    ts[ty][tx] = W[(long long)(blockIdx.y * 32 + ty) * 1024 + blockIdx.x * 32 + tx];
    __syncthreads();
    const float x = ts[tx][ty];
    const long long o = (long long)(blockIdx.x * 32 + ty) * 1024 + blockIdx.y * 32 + tx;
    T[o] = __half_as_ushort(__float2half_rn(x));
}

// ---------------------------------------------------------------------------
// Mask dtype detection (bool may arrive as u8/i32/f32)
// ---------------------------------------------------------------------------
__global__ void detect_mask_kernel(const unsigned char* __restrict__ m)
{
    __shared__ int bad_i32, bad_f32;
    if (threadIdx.x == 0) { bad_i32 = 0; bad_f32 = 0; }
    __syncthreads();
    const unsigned int* w = (const unsigned int*)m;
    for (int i = threadIdx.x; i < 2048; i += 256) {
        unsigned int x = w[i];
        if (x != 0u && x != 1u)          bad_i32 = 1;
        if (x != 0u && x != 0x3F800000u) bad_f32 = 1;
    }
    __syncthreads();
    if (threadIdx.x == 0)
        g_mask_mode = bad_i32 ? (bad_f32 ? 0 : 2) : 1;
}

// ---------------------------------------------------------------------------
// Masked softmax over rows of S (fp16) [B*TQ, 2048] -> P fp16, vectorized
// ---------------------------------------------------------------------------
__global__ void __launch_bounds__(256)
softmax_kernel(const u32* __restrict__ S32, const void* __restrict__ maskv,
               u32* __restrict__ P32)
{
    const long long base32 = (long long)blockIdx.x * 1024;   // 1024 u32 per row
    const int tid  = threadIdx.x;
    const int mode = g_mask_mode;

    float v[8];
    bool  keep[8];
#pragma unroll
    for (int i = 0; i < 4; i++) {
        const long long idx = base32 + tid + i * 256;
        const u32 w = S32[idx];
        const __half2 hv = *(const __half2*)&w;
        v[2*i]   = __half2float(__low2half(hv));
        v[2*i+1] = __half2float(__high2half(hv));
        if (mode == 1) {
            const int2 mm = ((const int2*)maskv)[idx];
            keep[2*i] = mm.x != 0; keep[2*i+1] = mm.y != 0;
        } else if (mode == 2) {
            const float2 mm = ((const float2*)maskv)[idx];
            keep[2*i] = mm.x != 0.0f; keep[2*i+1] = mm.y != 0.0f;
        } else {
            const uchar2 mm = ((const uchar2*)maskv)[idx];
            keep[2*i] = mm.x != 0; keep[2*i+1] = mm.y != 0;
        }
    }

    float mx = -3.0e38f;
#pragma unroll
    for (int i = 0; i < 8; i++)
        if (keep[i]) mx = fmaxf(mx, v[i]);

    __shared__ float red[8];
#pragma unroll
    for (int o = 16; o > 0; o >>= 1)
        mx = fmaxf(mx, __shfl_xor_sync(0xffffffffu, mx, o));
    if ((tid & 31) == 0) red[tid >> 5] = mx;
    __syncthreads();
    float bm = red[0];
#pragma unroll
    for (int i = 1; i < 8; i++) bm = fmaxf(bm, red[i]);

    float sum = 0.0f;
#pragma unroll
    for (int i = 0; i < 8; i++) {
        const float e = keep[i] ? __expf(v[i] - bm) : 0.0f;
        v[i] = e;
        sum += e;
    }
#pragma unroll
    for (int o = 16; o > 0; o >>= 1)
        sum += __shfl_xor_sync(0xffffffffu, sum, o);
    __syncthreads();
    if ((tid & 31) == 0) red[tid >> 5] = sum;
    __syncthreads();
    float ts = 0.0f;
#pragma unroll
    for (int i = 0; i < 8; i++) ts += red[i];

    const float inv = 1.0f / ts;
#pragma unroll
    for (int i = 0; i < 4; i++) {
        const __half2 hp = __floats2half2_rn(v[2*i] * inv, v[2*i+1] * inv);
        P32[base32 + tid + i * 256] = *(const u32*)&hp;
    }
}

// ---------------------------------------------------------------------------
// kernel_launch
// ---------------------------------------------------------------------------
extern "C" void kernel_launch(void* const* d_in, const int* in_sizes, int n_in,
                              void* d_out, int out_size)
{
    (void)in_sizes; (void)n_in; (void)out_size;

    const float* query = (const float*)d_in[0];
    const float* enc   = (const float*)d_in[1];
    const unsigned char* mask = (const unsigned char*)d_in[2];
    const float* Wq = (const float*)d_in[3];
    const float* bq = (const float*)d_in[4];
    const float* Wk = (const float*)d_in[5];
    const float* bk = (const float*)d_in[6];
    const float* Wv = (const float*)d_in[7];
    const float* bv = (const float*)d_in[8];
    float* out = (float*)d_out;

    h16 *Ef, *Xf, *Wqt, *Wkt, *Wvt;
    h16 *Q, *K, *V, *P, *Sp;
    cudaGetSymbolAddress((void**)&Ef,  g_Ef);
    cudaGetSymbolAddress((void**)&Xf,  g_Xf);
    cudaGetSymbolAddress((void**)&Wqt, g_Wq);
    cudaGetSymbolAddress((void**)&Wkt, g_Wk);
    cudaGetSymbolAddress((void**)&Wvt, g_Wv);
    cudaGetSymbolAddress((void**)&Q,   g_Q);
    cudaGetSymbolAddress((void**)&K,   g_K);
    cudaGetSymbolAddress((void**)&V,   g_V);
    cudaGetSymbolAddress((void**)&P,   g_P);
    cudaGetSymbolAddress((void**)&Sp,  g_S);

    constexpr int SMEM_T = 3 * (ABYTES + BBYTES_T);   // 110592
    constexpr int SMEM_N = 3 * (ABYTES + BBYTES_N);   // 107520
    cudaFuncSetAttribute(gemm_mma<0, true>,
                         cudaFuncAttributeMaxDynamicSharedMemorySize, SMEM_T);
    cudaFuncSetAttribute(gemm_mma<3, true>,
                         cudaFuncAttributeMaxDynamicSharedMemorySize, SMEM_T);
    cudaFuncSetAttribute(gemm_mma<2, false>,
                         cudaFuncAttributeMaxDynamicSharedMemorySize, SMEM_N);

    const int T = 2048;

    // 1) convert activations to fp16 (one launch for enc + query)
    conv_f16_2<<<32768, 256>>>((const float4*)enc, Ef, (const float4*)query, Xf);

    // 2) transpose+convert all 3 weights (one launch)
    dim3 wtg(32, 32, 3), wtb(32, 32);
    wt_conv3<<<wtg, wtb>>>(Wq, Wqt, Wk, Wkt, Wv, Wvt);

    detect_mask_kernel<<<1, 256>>>(mask);

    // 3) projections: pure fp16, fp16 outputs
    dim3 gp(1024 / BN, 16384 / BM, 1);
    gemm_mma<0, true><<<gp, 256, SMEM_T>>>(Ef, Wkt, bk,
        K, nullptr, 1024, 1024, 1024, 1024, 1.0f, 0, 0, 0);
    gemm_mma<0, true><<<gp, 256, SMEM_T>>>(Ef, Wvt, bv,
        V, nullptr, 1024, 1024, 1024, 1024, 1.0f, 0, 0, 0);
    gemm_mma<0, true><<<gp, 256, SMEM_T>>>(Xf, Wqt, bq,
        Q, nullptr, 1024, 1024, 1024, 1024, 1.0f, 0, 0, 0);

    // 4) scores: S = (Q K^T) / 32, fp16 out
    dim3 gs(T / BN, T / BM, 8);
    gemm_mma<3, true><<<gs, 256, SMEM_T>>>(Q, K, nullptr,
        Sp, nullptr, 1024, 1024, 2048, 1024, 0.03125f,
        2048LL * 1024, 2048LL * 1024, 2048LL * 2048);

    // 5) masked softmax (fp16 in/out, vectorized)
    softmax_kernel<<<8 * T, 256>>>((const u32*)Sp, (const void*)mask, (u32*)P);

    // 6) output: O = P V   (V NN layout, ldmatrix.trans), fp32 out
    dim3 go(1024 / BN, T / BM, 8);
    gemm_mma<2, false><<<go, 256, SMEM_N>>>(P, V, nullptr,
        nullptr, out, 2048, 1024, 1024, 2048, 1.0f,
        2048LL * 2048, 2048LL * 1024, 2048LL * 1024);
}

// round 17
// speedup vs baseline: 1.8712x; 1.0161x over previous
#include <cuda_runtime.h>
#include <cuda_fp16.h>

typedef unsigned short h16;    // opaque 16-bit payload (fp16 bits)
typedef unsigned int u32;
typedef unsigned long long u64;

// ---------------------------------------------------------------------------
// Problem constants: B=8, TQ=TK=2048, F=1024, H=1024
// ---------------------------------------------------------------------------
#define MTOT (16384LL * 1024)

static __device__ h16   g_Ef[MTOT];                           // encoder fp16
static __device__ h16   g_Xf[MTOT];                           // query fp16
static __device__ h16   g_Wq[1024*1024];                      // W^T fp16
static __device__ h16   g_Wk[1024*1024];
static __device__ h16   g_Wv[1024*1024];
static __device__ h16   g_Q[MTOT];                            // fp16
static __device__ h16   g_K[MTOT];                            // fp16
static __device__ h16   g_V[MTOT];                            // fp16 [b*2048+t][1024]
static __device__ h16   g_S[8LL * 2048 * 2048];               // scores fp16
static __device__ h16   g_P[8LL * 2048 * 2048];               // probs fp16
static __device__ int   g_mask_mode;

// ---------------------------------------------------------------------------
// PTX helpers (sm_80-era; legal under generic compute_103 target)
// ---------------------------------------------------------------------------
__device__ __forceinline__ u32 smem_u32(const void* p) {
    u32 a;
    asm("{ .reg .u64 t; cvta.to.shared.u64 t, %1; cvt.u32.u64 %0, t; }"
        : "=r"(a) : "l"(p));
    return a;
}
#define CP_ASYNC16(dst, src) \
    asm volatile("cp.async.cg.shared.global [%0], [%1], 16;" \
                 :: "r"(dst), "l"(src) : "memory")
#define CP_COMMIT() asm volatile("cp.async.commit_group;" ::: "memory")
#define CP_WAIT1()  asm volatile("cp.async.wait_group 1;" ::: "memory")

__device__ __forceinline__ void ldsm_x4(u32& r0, u32& r1, u32& r2, u32& r3, u32 a) {
    asm volatile("ldmatrix.sync.aligned.m8n8.x4.shared.b16 {%0,%1,%2,%3}, [%4];"
                 : "=r"(r0), "=r"(r1), "=r"(r2), "=r"(r3) : "r"(a));
}
__device__ __forceinline__ void ldsm_x4t(u32& r0, u32& r1, u32& r2, u32& r3, u32 a) {
    asm volatile("ldmatrix.sync.aligned.m8n8.x4.trans.shared.b16 {%0,%1,%2,%3}, [%4];"
                 : "=r"(r0), "=r"(r1), "=r"(r2), "=r"(r3) : "r"(a));
}
__device__ __forceinline__ void mma_f16(float* c, const u32* a, const u32* b) {
    asm volatile(
        "mma.sync.aligned.m16n8k16.row.col.f32.f16.f16.f32 "
        "{%0,%1,%2,%3}, {%4,%5,%6,%7}, {%8,%9}, {%0,%1,%2,%3};"
        : "+f"(c[0]), "+f"(c[1]), "+f"(c[2]), "+f"(c[3])
        : "r"(a[0]), "r"(a[1]), "r"(a[2]), "r"(a[3]), "r"(b[0]), "r"(b[1]));
}

// ---------------------------------------------------------------------------
// GEMM body: D[m,n] = sum_k A[m,k]*B'[k,n]   (pure fp16, 1 MMA per k-tile)
//   BT=true : B stored [N][K] -> ldmatrix; BT=false: B [K][N] -> ldmatrix.trans
//   MODE 0: fp16 out + bias;  MODE 2: fp32 out * alpha;  MODE 3: fp16 out * alpha
// CTA tile 128x128, BK=64, 3-stage cp.async pipeline, 256 threads (8 warps
// 2x4), TWO CTAs per SM, x4 B-fragment loads (6 LDSM per kk).
// ---------------------------------------------------------------------------
#define BM 128
#define BN 128
#define BKK 64
#define APITCH 72                            // 64 + 8 pad (16b units)
#define ABYTES (BM * APITCH * 2)             // 18432
#define BPITCH_T 72
#define BBYTES_T (BN * BPITCH_T * 2)         // 18432
#define BPITCH_N 136                         // 128 + 8 pad
#define BBYTES_N (BKK * BPITCH_N * 2)        // 17408

template <int MODE, bool BT>
__device__ __forceinline__ void
gemm_body(const h16* __restrict__ A, const h16* __restrict__ B,
          const float* __restrict__ bias,
          h16* __restrict__ C0, float* __restrict__ Cf,
          int lda, int ldb, int ldc, int K, float alpha, char* smem)
{
    constexpr int BBYTES  = BT ? BBYTES_T : BBYTES_N;
    constexpr int OFF_B   = ABYTES;
    constexpr int STAGE   = ABYTES + BBYTES;

    const u32 sb = smem_u32(smem);

    const int tid  = threadIdx.x;
    const int wid  = tid >> 5, lane = tid & 31;
    const int wm   = wid & 1, wn = wid >> 1;          // 2 x 4 warp grid

    const int m0 = blockIdx.y * BM;
    const int n0 = blockIdx.x * BN;

    // ---- loader geometry (BK=64, 256 threads) ----
    const int ar0 = tid >> 2, ac = (tid & 3) * 16;
    const int nr0 = tid >> 4, nc = (tid & 15) * 8;

    auto load_stage = [&](int t) {
        const long long kb = (long long)t * BKK;
        const u32 st = sb + (u32)((t % 3) * STAGE);
#pragma unroll
        for (int i = 0; i < 2; i++) {
            const int r = ar0 + i * 64;
            const long long g = (long long)(m0 + r) * lda + kb + ac;
            const u32 d = st + (u32)(r * APITCH + ac) * 2;
            CP_ASYNC16(d,      A + g);
            CP_ASYNC16(d + 16, A + g + 8);
        }
        if (BT) {
#pragma unroll
            for (int i = 0; i < 2; i++) {
                const int r = ar0 + i * 64;
                const long long g = (long long)(n0 + r) * ldb + kb + ac;
                const u32 d = st + OFF_B + (u32)(r * BPITCH_T + ac) * 2;
                CP_ASYNC16(d,      B + g);
                CP_ASYNC16(d + 16, B + g + 8);
            }
        } else {
#pragma unroll
            for (int i = 0; i < 4; i++) {
                const int r = nr0 + i * 16;
                const long long g = (kb + r) * (long long)ldb + n0 + nc;
                const u32 d = st + OFF_B + (u32)(r * BPITCH_N + nc) * 2;
                CP_ASYNC16(d, B + g);
            }
        }
    };

    // ---- ldmatrix per-lane offsets ----
    const int a_lr = (lane & 7) + ((lane >> 3) & 1) * 8;
    const int a_lk = (lane >> 4) * 8;
    u32 a_off[4];
#pragma unroll
    for (int mt = 0; mt < 4; mt++)
        a_off[mt] = (u32)((wm * 64 + mt * 16 + a_lr) * APITCH + a_lk) * 2;

    // B x4 offsets: one per nt-PAIR
    u32 b_off4[2];
    {
        const int l7 = lane & 7;
        const int kh = (lane >> 3) & 1;      // k-half select
        const int nh = (lane >> 4) & 1;      // nt-within-pair select
        if (BT) {
#pragma unroll
            for (int ntp = 0; ntp < 2; ntp++)
                b_off4[ntp] = (u32)(((wn * 32 + ntp * 16 + nh * 8 + l7) * BPITCH_T
                                     + kh * 8) * 2);
        } else {
#pragma unroll
            for (int ntp = 0; ntp < 2; ntp++)
                b_off4[ntp] = (u32)(((kh * 8 + l7) * BPITCH_N
                                     + wn * 32 + ntp * 16 + nh * 8) * 2);
        }
    }

    float acc[4][4][4];
#pragma unroll
    for (int i = 0; i < 4; i++)
#pragma unroll
        for (int j = 0; j < 4; j++)
#pragma unroll
            for (int v = 0; v < 4; v++) acc[i][j][v] = 0.0f;

    u32 ah[4][4], bh[4][2];

    const int nst = K / BKK;

    load_stage(0); CP_COMMIT();
    load_stage(1); CP_COMMIT();

    for (int t = 0; t < nst; t++) {
        CP_WAIT1();
        __syncthreads();
        if (t + 2 < nst) load_stage(t + 2);
        CP_COMMIT();

        const u32 st  = sb + (u32)((t % 3) * STAGE);
        const u32 bAh = st;
        const u32 bBh = st + OFF_B;

#pragma unroll
        for (int kk = 0; kk < 4; kk++) {
            const u32 ak = (u32)(kk * 32);
            const u32 bk = BT ? (u32)(kk * 32) : (u32)(kk * 16 * BPITCH_N * 2);
#pragma unroll
            for (int ntp = 0; ntp < 2; ntp++) {
                if (BT)
                    ldsm_x4(bh[2*ntp][0], bh[2*ntp][1],
                            bh[2*ntp+1][0], bh[2*ntp+1][1],
                            bBh + b_off4[ntp] + bk);
                else
                    ldsm_x4t(bh[2*ntp][0], bh[2*ntp][1],
                             bh[2*ntp+1][0], bh[2*ntp+1][1],
                             bBh + b_off4[ntp] + bk);
            }
#pragma unroll
            for (int mt = 0; mt < 4; mt++)
                ldsm_x4(ah[mt][0], ah[mt][1], ah[mt][2], ah[mt][3],
                        bAh + a_off[mt] + ak);
#pragma unroll
            for (int mt = 0; mt < 4; mt++)
#pragma unroll
                for (int nt = 0; nt < 4; nt++)
                    mma_f16(acc[mt][nt], ah[mt], bh[nt]);
        }
    }

    // ---- epilogue ----
    const int gr = lane >> 2, gc = (lane & 3) * 2;
#pragma unroll
    for (int mt = 0; mt < 4; mt++) {
#pragma unroll
        for (int nt = 0; nt < 4; nt++) {
            const int m_ = m0 + wm * 64 + mt * 16 + gr;
            const int n_ = n0 + wn * 32 + nt * 8 + gc;
            const float* a4 = acc[mt][nt];
            if (MODE == 0) {
                const float b0 = bias[n_], b1 = bias[n_ + 1];
#pragma unroll
                for (int h = 0; h < 2; h++) {
                    const float v0 = a4[2 * h]     + b0;
                    const float v1 = a4[2 * h + 1] + b1;
                    const long long o = (long long)(m_ + 8 * h) * ldc + n_;
                    h16 hp[2] = { __half_as_ushort(__float2half_rn(v0)),
                                  __half_as_ushort(__float2half_rn(v1)) };
                    *(u32*)(C0 + o) = *(const u32*)hp;
                }
            } else if (MODE == 3) {
#pragma unroll
                for (int h = 0; h < 2; h++) {
                    const long long o = (long long)(m_ + 8 * h) * ldc + n_;
                    h16 hp[2] = { __half_as_ushort(__float2half_rn(a4[2*h]   * alpha)),
                                  __half_as_ushort(__float2half_rn(a4[2*h+1] * alpha)) };
                    *(u32*)(C0 + o) = *(const u32*)hp;
                }
            } else {
#pragma unroll
                for (int h = 0; h < 2; h++) {
                    const long long o = (long long)(m_ + 8 * h) * ldc + n_;
                    float2 v = make_float2(a4[2 * h] * alpha, a4[2 * h + 1] * alpha);
                    *(float2*)(Cf + o) = v;
                }
            }
        }
    }
}

// Batched GEMM wrapper (scores / PV): blockIdx.z = batch index
template <int MODE, bool BT>
__global__ void __launch_bounds__(256, 2)
gemm_mma(const h16* __restrict__ A, const h16* __restrict__ B,
         h16* __restrict__ C0, float* __restrict__ Cf,
         int lda, int ldb, int ldc, int K, float alpha,
         long long sA, long long sB, long long sC)
{
    extern __shared__ char smem[];
    const long long z = blockIdx.z;
    gemm_body<MODE, BT>(A + z * sA, B + z * sB, nullptr,
                        C0 ? C0 + z * sC : nullptr,
                        Cf ? Cf + z * sC : nullptr,
                        lda, ldb, ldc, K, alpha, smem);
}

// Fused 3-projection wrapper: blockIdx.z selects (A, W, bias, C)
__global__ void __launch_bounds__(256, 2)
gemm_proj3(const float* __restrict__ bk, const float* __restrict__ bv,
           const float* __restrict__ bq)
{
    extern __shared__ char smem[];
    const int zi = blockIdx.z;
    const h16* A;
    const h16* B;
    const float* bias;
    h16* C;
    if (zi == 0)      { A = g_Ef; B = g_Wk; bias = bk; C = g_K; }
    else if (zi == 1) { A = g_Ef; B = g_Wv; bias = bv; C = g_V; }
    else              { A = g_Xf; B = g_Wq; bias = bq; C = g_Q; }
    gemm_body<0, true>(A, B, bias, C, nullptr,
                       1024, 1024, 1024, 1024, 1.0f, smem);
}

// ---------------------------------------------------------------------------
// fp32 -> single fp16 conversion, both activations in one launch
// ---------------------------------------------------------------------------
__global__ void __launch_bounds__(256)
conv_f16_2(const float4* __restrict__ ina, h16* __restrict__ outa,
           const float4* __restrict__ inb, h16* __restrict__ outb)
{
    const bool second = blockIdx.x >= 16384;
    const long long i = ((long long)blockIdx.x - (second ? 16384 : 0)) * 256
                        + threadIdx.x;
    const float4 v = (second ? inb : ina)[i];
    h16 p[4] = { __half_as_ushort(__float2half_rn(v.x)),
                 __half_as_ushort(__float2half_rn(v.y)),
                 __half_as_ushort(__float2half_rn(v.z)),
                 __half_as_ushort(__float2half_rn(v.w)) };
    *(uint2*)&((second ? outb : outa)[i * 4]) = *(const uint2*)p;
}

// W [F=1024, H=1024] -> W^T single fp16 [H, F]; z selects which W
__global__ void wt_conv3(const float* __restrict__ W0, h16* __restrict__ T0,
                         const float* __restrict__ W1, h16* __restrict__ T1,
                         const float* __restrict__ W2, h16* __restrict__ T2)
{
    const float* W = (blockIdx.z == 0) ? W0 : (blockIdx.z == 1) ? W1 : W2;
    h16*         T = (blockIdx.z == 0) ? T0 : (blockIdx.z == 1) ? T1 : T2;
    __shared__ float ts[32][33];
    const int tx = threadIdx.x, ty = threadIdx.y;
    ts[ty][tx] = W[(long long)(blockIdx.y * 32 + ty) * 1024 + blockIdx.x * 32 + tx];
    __syncthreads();
    const float x = ts[tx][ty];
    const long long o = (long long)(blockIdx.x * 32 + ty) * 1024 + blockIdx.y * 32 + tx;
    T[o] = __half_as_ushort(__float2half_rn(x));
}

// ---------------------------------------------------------------------------
// Mask dtype detection (bool may arrive as u8/i32/f32)
// ---------------------------------------------------------------------------
__global__ void detect_mask_kernel(const unsigned char* __restrict__ m)
{
    __shared__ int bad_i32, bad_f32;
    if (threadIdx.x == 0) { bad_i32 = 0; bad_f32 = 0; }
    __syncthreads();
    const unsigned int* w = (const unsigned int*)m;
    for (int i = threadIdx.x; i < 2048; i += 256) {
        unsigned int x = w[i];
        if (x != 0u && x != 1u)          bad_i32 = 1;
        if (x != 0u && x != 0x3F800000u) bad_f32 = 1;
    }
    __syncthreads();
    if (threadIdx.x == 0)
        g_mask_mode = bad_i32 ? (bad_f32 ? 0 : 2) : 1;
}

// ---------------------------------------------------------------------------
// Masked softmax over rows of S (fp16) [B*TQ, 2048] -> P fp16, vectorized
// ---------------------------------------------------------------------------
__global__ void __launch_bounds__(256)
softmax_kernel(const u32* __restrict__ S32, const void* __restrict__ maskv,
               u32* __restrict__ P32)
{
    const long long base32 = (long long)blockIdx.x * 1024;   // 1024 u32 per row
    const int tid  = threadIdx.x;
    const int mode = g_mask_mode;

    float v[8];
    bool  keep[8];
#pragma unroll
    for (int i = 0; i < 4; i++) {
        const long long idx = base32 + tid + i * 256;
        const u32 w = S32[idx];
        const __half2 hv = *(const __half2*)&w;
        v[2*i]   = __half2float(__low2half(hv));
        v[2*i+1] = __half2float(__high2half(hv));
        if (mode == 1) {
            const int2 mm = ((const int2*)maskv)[idx];
            keep[2*i] = mm.x != 0; keep[2*i+1] = mm.y != 0;
        } else if (mode == 2) {
            const float2 mm = ((const float2*)maskv)[idx];
            keep[2*i] = mm.x != 0.0f; keep[2*i+1] = mm.y != 0.0f;
        } else {
            const uchar2 mm = ((const uchar2*)maskv)[idx];
            keep[2*i] = mm.x != 0; keep[2*i+1] = mm.y != 0;
        }
    }

    float mx = -3.0e38f;
#pragma unroll
    for (int i = 0; i < 8; i++)
        if (keep[i]) mx = fmaxf(mx, v[i]);

    __shared__ float red[8];
#pragma unroll
    for (int o = 16; o > 0; o >>= 1)
        mx = fmaxf(mx, __shfl_xor_sync(0xffffffffu, mx, o));
    if ((tid & 31) == 0) red[tid >> 5] = mx;
    __syncthreads();
    float bm = red[0];
#pragma unroll
    for (int i = 1; i < 8; i++) bm = fmaxf(bm, red[i]);

    float sum = 0.0f;
#pragma unroll
    for (int i = 0; i < 8; i++) {
        const float e = keep[i] ? __expf(v[i] - bm) : 0.0f;
        v[i] = e;
        sum += e;
    }
#pragma unroll
    for (int o = 16; o > 0; o >>= 1)
        sum += __shfl_xor_sync(0xffffffffu, sum, o);
    __syncthreads();
    if ((tid & 31) == 0) red[tid >> 5] = sum;
    __syncthreads();
    float ts = 0.0f;
#pragma unroll
    for (int i = 0; i < 8; i++) ts += red[i];

    const float inv = 1.0f / ts;
#pragma unroll
    for (int i = 0; i < 4; i++) {
        const __half2 hp = __floats2half2_rn(v[2*i] * inv, v[2*i+1] * inv);
        P32[base32 + tid + i * 256] = *(const u32*)&hp;
    }
}

// ---------------------------------------------------------------------------
// kernel_launch
// ---------------------------------------------------------------------------
extern "C" void kernel_launch(void* const* d_in, const int* in_sizes, int n_in,
                              void* d_out, int out_size)
{
    (void)in_sizes; (void)n_in; (void)out_size;

    const float* query = (const float*)d_in[0];
    const float* enc   = (const float*)d_in[1];
    const unsigned char* mask = (const unsigned char*)d_in[2];
    const float* Wq = (const float*)d_in[3];
    const float* bq = (const float*)d_in[4];
    const float* Wk = (const float*)d_in[5];
    const float* bk = (const float*)d_in[6];
    const float* Wv = (const float*)d_in[7];
    const float* bv = (const float*)d_in[8];
    float* out = (float*)d_out;

    h16 *Ef, *Xf, *Wqt, *Wkt, *Wvt;
    h16 *Q, *K, *V, *P, *Sp;
    cudaGetSymbolAddress((void**)&Ef,  g_Ef);
    cudaGetSymbolAddress((void**)&Xf,  g_Xf);
    cudaGetSymbolAddress((void**)&Wqt, g_Wq);
    cudaGetSymbolAddress((void**)&Wkt, g_Wk);
    cudaGetSymbolAddress((void**)&Wvt, g_Wv);
    cudaGetSymbolAddress((void**)&Q,   g_Q);
    cudaGetSymbolAddress((void**)&K,   g_K);
    cudaGetSymbolAddress((void**)&V,   g_V);
    cudaGetSymbolAddress((void**)&P,   g_P);
    cudaGetSymbolAddress((void**)&Sp,  g_S);

    constexpr int SMEM_T = 3 * (ABYTES + BBYTES_T);   // 110592
    constexpr int SMEM_N = 3 * (ABYTES + BBYTES_N);   // 107520
    cudaFuncSetAttribute(gemm_proj3,
                         cudaFuncAttributeMaxDynamicSharedMemorySize, SMEM_T);
    cudaFuncSetAttribute(gemm_mma<3, true>,
                         cudaFuncAttributeMaxDynamicSharedMemorySize, SMEM_T);
    cudaFuncSetAttribute(gemm_mma<2, false>,
                         cudaFuncAttributeMaxDynamicSharedMemorySize, SMEM_N);

    const int T = 2048;

    // 1) convert activations to fp16 (one launch for enc + query)
    conv_f16_2<<<32768, 256>>>((const float4*)enc, Ef, (const float4*)query, Xf);

    // 2) transpose+convert all 3 weights (one launch)
    dim3 wtg(32, 32, 3), wtb(32, 32);
    wt_conv3<<<wtg, wtb>>>(Wq, Wqt, Wk, Wkt, Wv, Wvt);

    detect_mask_kernel<<<1, 256>>>(mask);

    // 3) all three projections in ONE launch (z selects A/W/bias/C)
    dim3 gp(1024 / BN, 16384 / BM, 3);
    gemm_proj3<<<gp, 256, SMEM_T>>>(bk, bv, bq);

    // 4) scores: S = (Q K^T) / 32, fp16 out
    dim3 gs(T / BN, T / BM, 8);
    gemm_mma<3, true><<<gs, 256, SMEM_T>>>(Q, K, Sp, nullptr,
        1024, 1024, 2048, 1024, 0.03125f,
        2048LL * 1024, 2048LL * 1024, 2048LL * 2048);

    // 5) masked softmax (fp16 in/out, vectorized)
    softmax_kernel<<<8 * T, 256>>>((const u32*)Sp, (const void*)mask, (u32*)P);

    // 6) output: O = P V   (V NN layout, ldmatrix.trans), fp32 out
    dim3 go(1024 / BN, T / BM, 8);
    gemm_mma<2, false><<<go, 256, SMEM_N>>>(P, V, nullptr, out,
        2048, 1024, 1024, 2048, 1.0f,
        2048LL * 2048, 2048LL * 1024, 2048LL * 1024);
}